// round 2
// baseline (speedup 1.0000x reference)
#include <cuda_runtime.h>
#include <cstdint>
#include <math.h>

#define NROWS 204800
#define NC    256
#define NG    2048
#define NPGC  100
#define RB    3200          // NROWS/64

// ---- scratch (device globals; allocation is forbidden) ----
__device__ float d_Y0[NROWS * NC];
__device__ float d_Y1[NROWS * NC];
__device__ float d_psum  [2 * RB * 256];
__device__ float d_psumsq[2 * RB * 256];
__device__ float d_psum2  [16 * 256];
__device__ float d_psumsq2[16 * 256];
__device__ float d_bnscale[512];
__device__ float d_bnshift[512];
__device__ float d_wu[16 * 256];     // rows 0..7: ws_h ; rows 8..15: u_h
__device__ float d_cconst[1];
__device__ float d_st[NROWS * 16];   // per row: [scores(8) | t(8)]

// ---- packed f32x2 helpers ----
__device__ __forceinline__ unsigned long long dup2(float a) {
    unsigned long long r; unsigned ai = __float_as_uint(a);
    asm("mov.b64 %0, {%1, %1};" : "=l"(r) : "r"(ai));
    return r;
}
__device__ __forceinline__ void ffma2(unsigned long long& d, unsigned long long a, unsigned long long b) {
    asm("fma.rn.f32x2 %0, %1, %2, %0;" : "+l"(d) : "l"(a), "l"(b));
}
__device__ __forceinline__ float lo32(unsigned long long v) { return __uint_as_float((unsigned)(v & 0xffffffffull)); }
__device__ __forceinline__ float hi32(unsigned long long v) { return __uint_as_float((unsigned)(v >> 32)); }

constexpr int BM   = 64;
constexpr int BK   = 16;
constexpr int ASTR = 68;
constexpr int BSTR = 260;
constexpr int SM_FLOATS = BK * ASTR + BK * BSTR;   // 5248 floats

// ============================================================================
// Kernel 1: fold weights -> ws_h, u_h, cconst
// ============================================================================
__global__ void prep_kernel(const float* __restrict__ ipW, const float* __restrict__ ipb,
                            const float* __restrict__ opW, const float* __restrict__ opb,
                            const float* __restrict__ rW,  const float* __restrict__ rb)
{
    __shared__ float q[256];
    __shared__ float r2[256];
    __shared__ float red[256];
    const int tid = threadIdx.x;

    float s = 0.f;
    for (int k = 0; k < 256; k += 4) {
        float4 v = *reinterpret_cast<const float4*>(&ipW[tid * 256 + k]);
        s += v.x + v.y + v.z + v.w;
    }
    q[tid] = (s + ipb[tid]) * 0.17677669529663687f;   // 1/sqrt(32)

    float s2 = 0.f;
    for (int c = 0; c < 256; c++) s2 += rW[c] * opW[c * 256 + tid];
    r2[tid] = s2;
    __syncthreads();

    const int c = tid;
    for (int h = 0; h < 8; h++) {
        float a = 0.f, u = 0.f;
        #pragma unroll 8
        for (int d = 0; d < 32; d++) {
            a += q [h * 32 + d] * ipW[(256 + h * 32 + d) * 256 + c];
            u += r2[h * 32 + d] * ipW[(512 + h * 32 + d) * 256 + c];
        }
        d_wu[h * 256 + c]       = a;
        d_wu[(8 + h) * 256 + c] = u;
    }

    red[tid] = ipb[512 + tid] * r2[tid] + rW[tid] * opb[tid];
    __syncthreads();
    for (int off = 128; off; off >>= 1) {
        if (tid < off) red[tid] += red[tid + off];
        __syncthreads();
    }
    if (tid == 0) d_cconst[0] = red[0] + rb[0];
}

// ============================================================================
// Kernel 2: Y = X @ W^T + b (both paths) + per-rowblock column sum/sumsq
// ============================================================================
__global__ __launch_bounds__(256, 2)
void gemm_bn_stats(const float* __restrict__ X0, const float* __restrict__ X1,
                   const float* __restrict__ W0, const float* __restrict__ B0,
                   const float* __restrict__ W1, const float* __restrict__ B1)
{
    __shared__ __align__(16) float smbuf[SM_FLOATS];
    float* As = smbuf;
    float* Bs = smbuf + BK * ASTR;

    const int mat = blockIdx.y;
    const float* __restrict__ X    = mat ? X1 : X0;
    const float* __restrict__ W    = mat ? W1 : W0;
    const float* __restrict__ bias = mat ? B1 : B0;

    const int tid  = threadIdx.x;
    const int ty   = tid >> 5;
    const int tx   = tid & 31;
    const int row0 = blockIdx.x * BM;
    const int a_row = tid >> 2;
    const int a_kq  = (tid & 3) << 2;

    unsigned long long acc2[8][4];
    #pragma unroll
    for (int i = 0; i < 8; i++)
        #pragma unroll
        for (int p = 0; p < 4; p++) acc2[i][p] = 0ull;

    float4 av = *reinterpret_cast<const float4*>(&X[(row0 + a_row) * NC + a_kq]);
    float4 bv[4];
    #pragma unroll
    for (int i = 0; i < 4; i++) {
        int idx = tid + 256 * i; int j = idx >> 2; int kq = (idx & 3) << 2;
        bv[i] = *reinterpret_cast<const float4*>(&W[j * NC + kq]);
    }

    for (int kt = 0; kt < NC; kt += BK) {
        __syncthreads();
        As[(a_kq + 0) * ASTR + a_row] = av.x;
        As[(a_kq + 1) * ASTR + a_row] = av.y;
        As[(a_kq + 2) * ASTR + a_row] = av.z;
        As[(a_kq + 3) * ASTR + a_row] = av.w;
        #pragma unroll
        for (int i = 0; i < 4; i++) {
            int idx = tid + 256 * i; int j = idx >> 2; int kq = (idx & 3) << 2;
            Bs[(kq + 0) * BSTR + j] = bv[i].x;
            Bs[(kq + 1) * BSTR + j] = bv[i].y;
            Bs[(kq + 2) * BSTR + j] = bv[i].z;
            Bs[(kq + 3) * BSTR + j] = bv[i].w;
        }
        __syncthreads();

        int ktn = kt + BK; if (ktn >= NC) ktn = kt;
        av = *reinterpret_cast<const float4*>(&X[(row0 + a_row) * NC + ktn + a_kq]);
        #pragma unroll
        for (int i = 0; i < 4; i++) {
            int idx = tid + 256 * i; int j = idx >> 2; int kq = (idx & 3) << 2;
            bv[i] = *reinterpret_cast<const float4*>(&W[j * NC + ktn + kq]);
        }

        #pragma unroll
        for (int k = 0; k < BK; k++) {
            const float4 aA = *reinterpret_cast<const float4*>(&As[k * ASTR + ty * 8]);
            const float4 aB = *reinterpret_cast<const float4*>(&As[k * ASTR + ty * 8 + 4]);
            const ulonglong2 b01 = *reinterpret_cast<const ulonglong2*>(&Bs[k * BSTR + tx * 8]);
            const ulonglong2 b23 = *reinterpret_cast<const ulonglong2*>(&Bs[k * BSTR + tx * 8 + 4]);
            const float a[8] = {aA.x, aA.y, aA.z, aA.w, aB.x, aB.y, aB.z, aB.w};
            #pragma unroll
            for (int i = 0; i < 8; i++) {
                unsigned long long ad = dup2(a[i]);
                ffma2(acc2[i][0], ad, b01.x);
                ffma2(acc2[i][1], ad, b01.y);
                ffma2(acc2[i][2], ad, b23.x);
                ffma2(acc2[i][3], ad, b23.y);
            }
        }
    }

    float acc[8][8];
    #pragma unroll
    for (int i = 0; i < 8; i++)
        #pragma unroll
        for (int p = 0; p < 4; p++) {
            acc[i][2 * p]     = lo32(acc2[i][p]);
            acc[i][2 * p + 1] = hi32(acc2[i][p]);
        }
    const float4 bb0 = *reinterpret_cast<const float4*>(&bias[tx * 8]);
    const float4 bb1 = *reinterpret_cast<const float4*>(&bias[tx * 8 + 4]);
    #pragma unroll
    for (int i = 0; i < 8; i++) {
        acc[i][0] += bb0.x; acc[i][1] += bb0.y; acc[i][2] += bb0.z; acc[i][3] += bb0.w;
        acc[i][4] += bb1.x; acc[i][5] += bb1.y; acc[i][6] += bb1.z; acc[i][7] += bb1.w;
    }
    float* __restrict__ Y = mat ? d_Y1 : d_Y0;
    #pragma unroll
    for (int i = 0; i < 8; i++) {
        const int rg = row0 + ty * 8 + i;
        *reinterpret_cast<float4*>(&Y[rg * NC + tx * 8])     = make_float4(acc[i][0], acc[i][1], acc[i][2], acc[i][3]);
        *reinterpret_cast<float4*>(&Y[rg * NC + tx * 8 + 4]) = make_float4(acc[i][4], acc[i][5], acc[i][6], acc[i][7]);
    }

    float cs[8], cq[8];
    #pragma unroll
    for (int j = 0; j < 8; j++) { cs[j] = 0.f; cq[j] = 0.f; }
    #pragma unroll
    for (int i = 0; i < 8; i++)
        #pragma unroll
        for (int j = 0; j < 8; j++) { const float v = acc[i][j]; cs[j] += v; cq[j] += v * v; }

    __syncthreads();
    #pragma unroll
    for (int j = 0; j < 8; j++) smbuf[ty * 256 + tx * 8 + j] = cs[j];
    __syncthreads();
    {
        float s = 0.f;
        #pragma unroll
        for (int y = 0; y < 8; y++) s += smbuf[y * 256 + tid];
        d_psum[(mat * RB + blockIdx.x) * 256 + tid] = s;
    }
    __syncthreads();
    #pragma unroll
    for (int j = 0; j < 8; j++) smbuf[ty * 256 + tx * 8 + j] = cq[j];
    __syncthreads();
    {
        float s = 0.f;
        #pragma unroll
        for (int y = 0; y < 8; y++) s += smbuf[y * 256 + tid];
        d_psumsq[(mat * RB + blockIdx.x) * 256 + tid] = s;
    }
}

// ============================================================================
// Kernels 3/4: deterministic hierarchical stat reduction -> BN scale/shift
// ============================================================================
__global__ void stats_partial()
{
    const int mat = blockIdx.x >> 3;
    const int sl  = blockIdx.x & 7;
    const int col = threadIdx.x;
    float s = 0.f, q = 0.f;
    const int rb0 = sl * (RB / 8);
    for (int rbi = rb0; rbi < rb0 + (RB / 8); rbi++) {
        s += d_psum  [(mat * RB + rbi) * 256 + col];
        q += d_psumsq[(mat * RB + rbi) * 256 + col];
    }
    d_psum2  [blockIdx.x * 256 + col] = s;
    d_psumsq2[blockIdx.x * 256 + col] = q;
}

__global__ void stats_final(const float* __restrict__ g0, const float* __restrict__ be0,
                            const float* __restrict__ g1, const float* __restrict__ be1)
{
    const int mat = blockIdx.x;
    const int col = threadIdx.x;
    float s = 0.f, q = 0.f;
    #pragma unroll
    for (int sl = 0; sl < 8; sl++) {
        s += d_psum2  [(mat * 8 + sl) * 256 + col];
        q += d_psumsq2[(mat * 8 + sl) * 256 + col];
    }
    const float inv  = 1.0f / (float)NROWS;
    const float mean = s * inv;
    const float var  = fmaxf(q * inv - mean * mean, 0.f);
    const float* gg = mat ? g1 : g0;
    const float* bb = mat ? be1 : be0;
    const float sc = gg[col] * rsqrtf(var + 1e-5f);
    d_bnscale[mat * 256 + col] = sc;
    d_bnshift[mat * 256 + col] = bb[col] - mean * sc;
}

// ============================================================================
// Kernel 5: fused BN+ReLU -> merge GEMM -> scores/t epilogue (x not stored)
// ============================================================================
__global__ __launch_bounds__(256, 2)
void gemm_merge(const float* __restrict__ Wm, const float* __restrict__ bm)
{
    __shared__ __align__(16) float smbuf[SM_FLOATS];
    __shared__ float s_scale[512];
    __shared__ float s_shift[512];
    __shared__ __align__(16) float s_wu[16 * 256];
    float* As = smbuf;
    float* Bs = smbuf + BK * ASTR;

    const int tid  = threadIdx.x;
    const int ty   = tid >> 5;
    const int tx   = tid & 31;
    const int row0 = blockIdx.x * BM;
    const int a_row = tid >> 2;
    const int a_kq  = (tid & 3) << 2;

    for (int i = tid; i < 512; i += 256) { s_scale[i] = d_bnscale[i]; s_shift[i] = d_bnshift[i]; }
    for (int i = tid; i < 4096; i += 256) s_wu[i] = d_wu[i];

    unsigned long long acc2[8][4];
    #pragma unroll
    for (int i = 0; i < 8; i++)
        #pragma unroll
        for (int p = 0; p < 4; p++) acc2[i][p] = 0ull;

    float4 av = *reinterpret_cast<const float4*>(&d_Y0[(row0 + a_row) * NC + a_kq]);
    float4 bv[4];
    #pragma unroll
    for (int i = 0; i < 4; i++) {
        int idx = tid + 256 * i; int j = idx >> 2; int kq = (idx & 3) << 2;
        bv[i] = *reinterpret_cast<const float4*>(&Wm[j * 512 + kq]);
    }

    for (int kt = 0; kt < 512; kt += BK) {
        __syncthreads();
        {
            const int gk = kt + a_kq;
            As[(a_kq + 0) * ASTR + a_row] = fmaxf(fmaf(av.x, s_scale[gk + 0], s_shift[gk + 0]), 0.f);
            As[(a_kq + 1) * ASTR + a_row] = fmaxf(fmaf(av.y, s_scale[gk + 1], s_shift[gk + 1]), 0.f);
            As[(a_kq + 2) * ASTR + a_row] = fmaxf(fmaf(av.z, s_scale[gk + 2], s_shift[gk + 2]), 0.f);
            As[(a_kq + 3) * ASTR + a_row] = fmaxf(fmaf(av.w, s_scale[gk + 3], s_shift[gk + 3]), 0.f);
        }
        #pragma unroll
        for (int i = 0; i < 4; i++) {
            int idx = tid + 256 * i; int j = idx >> 2; int kq = (idx & 3) << 2;
            Bs[(kq + 0) * BSTR + j] = bv[i].x;
            Bs[(kq + 1) * BSTR + j] = bv[i].y;
            Bs[(kq + 2) * BSTR + j] = bv[i].z;
            Bs[(kq + 3) * BSTR + j] = bv[i].w;
        }
        __syncthreads();

        int ktn = kt + BK; if (ktn >= 512) ktn = kt;
        {
            const int gk = ktn + a_kq;
            const float* __restrict__ Ys = (gk < 256) ? d_Y0 : d_Y1;
            av = *reinterpret_cast<const float4*>(&Ys[(row0 + a_row) * NC + (gk & 255)]);
        }
        #pragma unroll
        for (int i = 0; i < 4; i++) {
            int idx = tid + 256 * i; int j = idx >> 2; int kq = (idx & 3) << 2;
            bv[i] = *reinterpret_cast<const float4*>(&Wm[j * 512 + ktn + kq]);
        }

        #pragma unroll
        for (int k = 0; k < BK; k++) {
            const float4 aA = *reinterpret_cast<const float4*>(&As[k * ASTR + ty * 8]);
            const float4 aB = *reinterpret_cast<const float4*>(&As[k * ASTR + ty * 8 + 4]);
            const ulonglong2 b01 = *reinterpret_cast<const ulonglong2*>(&Bs[k * BSTR + tx * 8]);
            const ulonglong2 b23 = *reinterpret_cast<const ulonglong2*>(&Bs[k * BSTR + tx * 8 + 4]);
            const float a[8] = {aA.x, aA.y, aA.z, aA.w, aB.x, aB.y, aB.z, aB.w};
            #pragma unroll
            for (int i = 0; i < 8; i++) {
                unsigned long long ad = dup2(a[i]);
                ffma2(acc2[i][0], ad, b01.x);
                ffma2(acc2[i][1], ad, b01.y);
                ffma2(acc2[i][2], ad, b23.x);
                ffma2(acc2[i][3], ad, b23.y);
            }
        }
    }

    float acc[8][8];
    #pragma unroll
    for (int i = 0; i < 8; i++)
        #pragma unroll
        for (int p = 0; p < 4; p++) {
            acc[i][2 * p]     = lo32(acc2[i][p]);
            acc[i][2 * p + 1] = hi32(acc2[i][p]);
        }
    const float4 bb0 = *reinterpret_cast<const float4*>(&bm[tx * 8]);
    const float4 bb1 = *reinterpret_cast<const float4*>(&bm[tx * 8 + 4]);
    #pragma unroll
    for (int i = 0; i < 8; i++) {
        acc[i][0] += bb0.x; acc[i][1] += bb0.y; acc[i][2] += bb0.z; acc[i][3] += bb0.w;
        acc[i][4] += bb1.x; acc[i][5] += bb1.y; acc[i][6] += bb1.z; acc[i][7] += bb1.w;
    }

    #pragma unroll
    for (int h = 0; h < 16; h++) {
        const float4 w0 = *reinterpret_cast<const float4*>(&s_wu[h * 256 + tx * 8]);
        const float4 w1 = *reinterpret_cast<const float4*>(&s_wu[h * 256 + tx * 8 + 4]);
        #pragma unroll
        for (int i = 0; i < 8; i++) {
            float v = acc[i][0] * w0.x + acc[i][1] * w0.y + acc[i][2] * w0.z + acc[i][3] * w0.w
                    + acc[i][4] * w1.x + acc[i][5] * w1.y + acc[i][6] * w1.z + acc[i][7] * w1.w;
            #pragma unroll
            for (int off = 16; off; off >>= 1) v += __shfl_down_sync(0xffffffffu, v, off);
            if (tx == 0) d_st[(row0 + ty * 8 + i) * 16 + h] = v;
        }
    }
}

// ============================================================================
// Kernel 6: per-group softmax-weighted mean + tanh readout
// ============================================================================
__global__ void groups_kernel(float* __restrict__ out)
{
    __shared__ float sb[NPGC * 16];
    __shared__ float hv[8];
    const int g = blockIdx.x;
    const int tid = threadIdx.x;
    const float* __restrict__ base = d_st + g * (NPGC * 16);
    for (int i = tid; i < NPGC * 16; i += 256) sb[i] = base[i];
    __syncthreads();

    const int h    = tid >> 5;
    const int lane = tid & 31;

    float mx = -1e30f;
    for (int r = lane; r < NPGC; r += 32) mx = fmaxf(mx, sb[r * 16 + h]);
    #pragma unroll
    for (int off = 16; off; off >>= 1) mx = fmaxf(mx, __shfl_xor_sync(0xffffffffu, mx, off));

    float num = 0.f, den = 0.f;
    for (int r = lane; r < NPGC; r += 32) {
        const float e = expf(sb[r * 16 + h] - mx);
        num = fmaf(e, sb[r * 16 + 8 + h], num);
        den += e;
    }
    #pragma unroll
    for (int off = 16; off; off >>= 1) {
        num += __shfl_xor_sync(0xffffffffu, num, off);
        den += __shfl_xor_sync(0xffffffffu, den, off);
    }
    if (lane == 0) hv[h] = num / den;
    __syncthreads();

    if (tid == 0) {
        float s = d_cconst[0];
        #pragma unroll
        for (int i = 0; i < 8; i++) s += hv[i];
        out[g] = tanhf(s);
    }
}

// ============================================================================
extern "C" void kernel_launch(void* const* d_in, const int* in_sizes, int n_in,
                              void* d_out, int out_size)
{
    const float* x0   = (const float*)d_in[0];
    const float* x1   = (const float*)d_in[1];
    // d_in[2] = batch (int64) — groups are contiguous NPGC-row chunks; not needed
    const float* p0W  = (const float*)d_in[3];
    const float* p0b  = (const float*)d_in[4];
    const float* p0g  = (const float*)d_in[5];
    const float* p0be = (const float*)d_in[6];
    const float* p1W  = (const float*)d_in[7];
    const float* p1b  = (const float*)d_in[8];
    const float* p1g  = (const float*)d_in[9];
    const float* p1be = (const float*)d_in[10];
    const float* mW   = (const float*)d_in[11];
    const float* mb   = (const float*)d_in[12];
    const float* ipW  = (const float*)d_in[13];
    const float* ipb  = (const float*)d_in[14];
    const float* opW  = (const float*)d_in[15];
    const float* opb  = (const float*)d_in[16];
    const float* rW   = (const float*)d_in[17];
    const float* rb   = (const float*)d_in[18];
    float* out = (float*)d_out;

    prep_kernel<<<1, 256>>>(ipW, ipb, opW, opb, rW, rb);
    gemm_bn_stats<<<dim3(RB, 2), 256>>>(x0, x1, p0W, p0b, p1W, p1b);
    stats_partial<<<16, 256>>>();
    stats_final<<<2, 256>>>(p0g, p0be, p1g, p1be);
    gemm_merge<<<RB, 256>>>(mW, mb);
    groups_kernel<<<NG, 256>>>(out);
}

// round 3
// speedup vs baseline: 1.3370x; 1.3370x over previous
#include <cuda_runtime.h>
#include <cstdint>
#include <math.h>

#define NROWS 204800
#define NG    2048
#define NPGC  100
#define MB    1600            // NROWS / 128

// ---- scratch (device globals; allocation forbidden) ----
__device__ float d_Y0[NROWS * 256];
__device__ float d_Y1[NROWS * 256];
__device__ float d_psum  [2 * MB * 256];
__device__ float d_psumsq[2 * MB * 256];
__device__ float d_psum2  [16 * 256];
__device__ float d_psumsq2[16 * 256];
__device__ float d_bnscale[512];
__device__ float d_bnshift[512];
__device__ float d_wu[16 * 256];        // rows 0..7: ws_h ; rows 8..15: u_h
__device__ float d_cconst[1];
__device__ float d_stp[2][NROWS * 16];  // per-nblk partial [scores(8)|t(8)]

// ---- tf32 helpers ----
__device__ __forceinline__ unsigned f2tf(float f) {
    unsigned u; asm("cvt.rna.tf32.f32 %0, %1;" : "=r"(u) : "f"(f)); return u;
}
__device__ __forceinline__ void mma_tf32(float c[4],
    unsigned a0, unsigned a1, unsigned a2, unsigned a3, unsigned b0, unsigned b1)
{
    asm volatile(
        "mma.sync.aligned.m16n8k8.row.col.f32.tf32.tf32.f32 "
        "{%0,%1,%2,%3},{%4,%5,%6,%7},{%8,%9},{%0,%1,%2,%3};"
        : "+f"(c[0]), "+f"(c[1]), "+f"(c[2]), "+f"(c[3])
        : "r"(a0), "r"(a1), "r"(a2), "r"(a3), "r"(b0), "r"(b1));
}

constexpr int KSTR  = 136;              // smem k-row stride (==8 mod 32 -> conflict-free frags)
constexpr int STAGE = 2 * 32 * KSTR;    // A(32xKSTR) + B(32xKSTR) per stage, in u32
constexpr int SMEM1 = 2 * STAGE * 4;                    // 69632 B
constexpr int SMEM2 = (2 * STAGE + 4096 + 1024) * 4;    // + wu + scale/shift = 90112 B

// ============================================================================
// Kernel 1: fold weights -> ws_h, u_h, cconst
// ============================================================================
__global__ void prep_kernel(const float* __restrict__ ipW, const float* __restrict__ ipb,
                            const float* __restrict__ opW, const float* __restrict__ opb,
                            const float* __restrict__ rW,  const float* __restrict__ rb)
{
    __shared__ float q[256];
    __shared__ float r2[256];
    __shared__ float red[256];
    const int tid = threadIdx.x;

    float s = 0.f;
    for (int k = 0; k < 256; k += 4) {
        float4 v = *reinterpret_cast<const float4*>(&ipW[tid * 256 + k]);
        s += v.x + v.y + v.z + v.w;
    }
    q[tid] = (s + ipb[tid]) * 0.17677669529663687f;   // 1/sqrt(32)

    float s2 = 0.f;
    for (int c = 0; c < 256; c++) s2 += rW[c] * opW[c * 256 + tid];
    r2[tid] = s2;
    __syncthreads();

    const int c = tid;
    for (int h = 0; h < 8; h++) {
        float a = 0.f, u = 0.f;
        #pragma unroll 8
        for (int d = 0; d < 32; d++) {
            a += q [h * 32 + d] * ipW[(256 + h * 32 + d) * 256 + c];
            u += r2[h * 32 + d] * ipW[(512 + h * 32 + d) * 256 + c];
        }
        d_wu[h * 256 + c]       = a;
        d_wu[(8 + h) * 256 + c] = u;
    }

    red[tid] = ipb[512 + tid] * r2[tid] + rW[tid] * opb[tid];
    __syncthreads();
    for (int off = 128; off; off >>= 1) {
        if (tid < off) red[tid] += red[tid + off];
        __syncthreads();
    }
    if (tid == 0) d_cconst[0] = red[0] + rb[0];
}

// ============================================================================
// Kernel 2: tf32 MMA GEMM  Y = X @ W^T + b  (both paths) + column stats
// grid (MB, 2 nblk, 2 mat), 256 threads, BM=128, BN=128, BK=32
// ============================================================================
__global__ __launch_bounds__(256, 1)
void gemm1(const float* __restrict__ X0, const float* __restrict__ X1,
           const float* __restrict__ W0, const float* __restrict__ B0,
           const float* __restrict__ W1, const float* __restrict__ B1)
{
    extern __shared__ unsigned sm[];
    const int mat  = blockIdx.z;
    const int nblk = blockIdx.y;
    const float* __restrict__ X    = mat ? X1 : X0;
    const float* __restrict__ W    = (mat ? W1 : W0) + nblk * 128 * 256;
    const float* __restrict__ bias = (mat ? B1 : B0) + nblk * 128;

    const int tid = threadIdx.x, lane = tid & 31, wid = tid >> 5;
    const int wm = wid >> 2, wn = wid & 3;
    const int r = lane >> 2, tq = lane & 3;
    const int row0 = blockIdx.x * 128;
    const int lm = tid & 127, kh = (tid >> 7) * 16;

    const float* __restrict__ Xp = X + (row0 + lm) * 256;
    const float* __restrict__ Wp = W + lm * 256;

    float4 rA[4], rB[4];
    #pragma unroll
    for (int j = 0; j < 4; j++) {
        rA[j] = *reinterpret_cast<const float4*>(Xp + kh + 4 * j);
        rB[j] = *reinterpret_cast<const float4*>(Wp + kh + 4 * j);
    }

    float acc[4][4][4];
    #pragma unroll
    for (int mi = 0; mi < 4; mi++)
        #pragma unroll
        for (int ni = 0; ni < 4; ni++)
            #pragma unroll
            for (int e = 0; e < 4; e++) acc[mi][ni][e] = 0.f;

    int s = 0;
    for (int kt = 0; kt < 256; kt += 32) {
        unsigned* As = sm + s * STAGE;
        unsigned* Bs = As + 32 * KSTR;
        #pragma unroll
        for (int j = 0; j < 4; j++) {
            const int kk = kh + 4 * j;
            As[(kk + 0) * KSTR + lm] = f2tf(rA[j].x);
            As[(kk + 1) * KSTR + lm] = f2tf(rA[j].y);
            As[(kk + 2) * KSTR + lm] = f2tf(rA[j].z);
            As[(kk + 3) * KSTR + lm] = f2tf(rA[j].w);
            Bs[(kk + 0) * KSTR + lm] = f2tf(rB[j].x);
            Bs[(kk + 1) * KSTR + lm] = f2tf(rB[j].y);
            Bs[(kk + 2) * KSTR + lm] = f2tf(rB[j].z);
            Bs[(kk + 3) * KSTR + lm] = f2tf(rB[j].w);
        }
        __syncthreads();
        if (kt + 32 < 256) {
            #pragma unroll
            for (int j = 0; j < 4; j++) {
                rA[j] = *reinterpret_cast<const float4*>(Xp + kt + 32 + kh + 4 * j);
                rB[j] = *reinterpret_cast<const float4*>(Wp + kt + 32 + kh + 4 * j);
            }
        }
        #pragma unroll
        for (int ks = 0; ks < 4; ks++) {
            const int kb = ks * 8;
            unsigned af[4][4], bf[4][2];
            #pragma unroll
            for (int mi = 0; mi < 4; mi++) {
                const int m0 = wm * 64 + mi * 16;
                af[mi][0] = As[(kb + tq) * KSTR + m0 + r];
                af[mi][1] = As[(kb + tq) * KSTR + m0 + r + 8];
                af[mi][2] = As[(kb + tq + 4) * KSTR + m0 + r];
                af[mi][3] = As[(kb + tq + 4) * KSTR + m0 + r + 8];
            }
            #pragma unroll
            for (int ni = 0; ni < 4; ni++) {
                const int n0 = wn * 32 + ni * 8;
                bf[ni][0] = Bs[(kb + tq) * KSTR + n0 + r];
                bf[ni][1] = Bs[(kb + tq + 4) * KSTR + n0 + r];
            }
            #pragma unroll
            for (int mi = 0; mi < 4; mi++)
                #pragma unroll
                for (int ni = 0; ni < 4; ni++)
                    mma_tf32(acc[mi][ni], af[mi][0], af[mi][1], af[mi][2], af[mi][3],
                             bf[ni][0], bf[ni][1]);
        }
        s ^= 1;
    }

    // ---- epilogue: bias, write Y, column stats ----
    float2 bb[4];
    #pragma unroll
    for (int ni = 0; ni < 4; ni++)
        bb[ni] = *reinterpret_cast<const float2*>(&bias[wn * 32 + ni * 8 + tq * 2]);
    #pragma unroll
    for (int mi = 0; mi < 4; mi++)
        #pragma unroll
        for (int ni = 0; ni < 4; ni++) {
            acc[mi][ni][0] += bb[ni].x; acc[mi][ni][1] += bb[ni].y;
            acc[mi][ni][2] += bb[ni].x; acc[mi][ni][3] += bb[ni].y;
        }

    float* __restrict__ Y = mat ? d_Y1 : d_Y0;
    const int colbase = nblk * 128 + wn * 32;
    #pragma unroll
    for (int mi = 0; mi < 4; mi++) {
        const int R0 = row0 + wm * 64 + mi * 16 + r;
        #pragma unroll
        for (int ni = 0; ni < 4; ni++) {
            const int gc = colbase + ni * 8 + tq * 2;
            *reinterpret_cast<float2*>(&Y[R0 * 256 + gc])       = make_float2(acc[mi][ni][0], acc[mi][ni][1]);
            *reinterpret_cast<float2*>(&Y[(R0 + 8) * 256 + gc]) = make_float2(acc[mi][ni][2], acc[mi][ni][3]);
        }
    }

    __syncthreads();           // safe to reuse sm
    float* ssum = reinterpret_cast<float*>(sm);       // [2][128]
    float* ssq  = ssum + 256;                         // [2][128]
    #pragma unroll
    for (int ni = 0; ni < 4; ni++) {
        float s0 = 0.f, s1 = 0.f, q0 = 0.f, q1 = 0.f;
        #pragma unroll
        for (int mi = 0; mi < 4; mi++) {
            const float v0 = acc[mi][ni][0], v1 = acc[mi][ni][1];
            const float v2 = acc[mi][ni][2], v3 = acc[mi][ni][3];
            s0 += v0 + v2; s1 += v1 + v3;
            q0 += v0 * v0 + v2 * v2; q1 += v1 * v1 + v3 * v3;
        }
        #pragma unroll
        for (int off = 4; off < 32; off <<= 1) {
            s0 += __shfl_xor_sync(0xffffffffu, s0, off);
            s1 += __shfl_xor_sync(0xffffffffu, s1, off);
            q0 += __shfl_xor_sync(0xffffffffu, q0, off);
            q1 += __shfl_xor_sync(0xffffffffu, q1, off);
        }
        if (lane < 4) {
            const int lcol = wn * 32 + ni * 8 + tq * 2;
            ssum[wm * 128 + lcol] = s0;  ssum[wm * 128 + lcol + 1] = s1;
            ssq [wm * 128 + lcol] = q0;  ssq [wm * 128 + lcol + 1] = q1;
        }
    }
    __syncthreads();
    if (tid < 128) {
        const int gidx = (mat * MB + blockIdx.x) * 256 + nblk * 128 + tid;
        d_psum  [gidx] = ssum[tid] + ssum[128 + tid];
        d_psumsq[gidx] = ssq [tid] + ssq [128 + tid];
    }
}

// ============================================================================
// Kernels 3/4: deterministic stat reduction -> BN scale/shift
// ============================================================================
__global__ void stats_partial()
{
    const int mat = blockIdx.x >> 3;
    const int sl  = blockIdx.x & 7;
    const int col = threadIdx.x;
    float s = 0.f, q = 0.f;
    const int rb0 = sl * (MB / 8);
    for (int rbi = rb0; rbi < rb0 + (MB / 8); rbi++) {
        s += d_psum  [(mat * MB + rbi) * 256 + col];
        q += d_psumsq[(mat * MB + rbi) * 256 + col];
    }
    d_psum2  [blockIdx.x * 256 + col] = s;
    d_psumsq2[blockIdx.x * 256 + col] = q;
}

__global__ void stats_final(const float* __restrict__ g0, const float* __restrict__ be0,
                            const float* __restrict__ g1, const float* __restrict__ be1)
{
    const int mat = blockIdx.x;
    const int col = threadIdx.x;
    float s = 0.f, q = 0.f;
    #pragma unroll
    for (int sl = 0; sl < 8; sl++) {
        s += d_psum2  [(mat * 8 + sl) * 256 + col];
        q += d_psumsq2[(mat * 8 + sl) * 256 + col];
    }
    const float inv  = 1.0f / (float)NROWS;
    const float mean = s * inv;
    const float var  = fmaxf(q * inv - mean * mean, 0.f);
    const float* gg = mat ? g1 : g0;
    const float* bb = mat ? be1 : be0;
    const float sc = gg[col] * rsqrtf(var + 1e-5f);
    d_bnscale[mat * 256 + col] = sc;
    d_bnshift[mat * 256 + col] = bb[col] - mean * sc;
}

// ============================================================================
// Kernel 5: tf32 MMA merge GEMM with fused BN+ReLU A-path and scores/t epilogue
// grid (MB, 2 nblk), 256 threads, K=512
// ============================================================================
__global__ __launch_bounds__(256, 1)
void gemm2(const float* __restrict__ Wm, const float* __restrict__ bm)
{
    extern __shared__ unsigned sm[];
    float* wuS    = reinterpret_cast<float*>(sm + 2 * STAGE);   // [16][256]
    float* scaleS = wuS + 4096;                                  // [512]
    float* shiftS = scaleS + 512;                                // [512]

    const int nblk = blockIdx.y;
    const int tid = threadIdx.x, lane = tid & 31, wid = tid >> 5;
    const int wm = wid >> 2, wn = wid & 3;
    const int r = lane >> 2, tq = lane & 3;
    const int row0 = blockIdx.x * 128;
    const int lm = tid & 127, kh = (tid >> 7) * 16;

    for (int i = tid; i < 4096; i += 256) wuS[i] = d_wu[i];
    for (int i = tid; i < 512; i += 256) { scaleS[i] = d_bnscale[i]; shiftS[i] = d_bnshift[i]; }
    __syncthreads();

    const float* __restrict__ Wp = Wm + (nblk * 128 + lm) * 512;

    float4 rA[4], rB[4];
    {
        const float* __restrict__ Ys = (kh < 256) ? d_Y0 : d_Y1;
        #pragma unroll
        for (int j = 0; j < 4; j++) {
            rA[j] = *reinterpret_cast<const float4*>(&Ys[lm * 256 + ((kh + 4 * j) & 255)]);
            rB[j] = *reinterpret_cast<const float4*>(Wp + kh + 4 * j);
        }
    }
    // note: rA row index is (row0+lm), fix below by using Ys + (row0+lm)*256 — redo properly:
    {
        const float* __restrict__ Ys = (kh < 256) ? d_Y0 : d_Y1;
        #pragma unroll
        for (int j = 0; j < 4; j++)
            rA[j] = *reinterpret_cast<const float4*>(&Ys[(row0 + lm) * 256 + ((kh + 4 * j) & 255)]);
    }

    float acc[4][4][4];
    #pragma unroll
    for (int mi = 0; mi < 4; mi++)
        #pragma unroll
        for (int ni = 0; ni < 4; ni++)
            #pragma unroll
            for (int e = 0; e < 4; e++) acc[mi][ni][e] = 0.f;

    int s = 0;
    for (int kt = 0; kt < 512; kt += 32) {
        unsigned* As = sm + s * STAGE;
        unsigned* Bs = As + 32 * KSTR;
        #pragma unroll
        for (int j = 0; j < 4; j++) {
            const int kk = kh + 4 * j;
            const int gk = kt + kk;
            As[(kk + 0) * KSTR + lm] = f2tf(fmaxf(fmaf(rA[j].x, scaleS[gk + 0], shiftS[gk + 0]), 0.f));
            As[(kk + 1) * KSTR + lm] = f2tf(fmaxf(fmaf(rA[j].y, scaleS[gk + 1], shiftS[gk + 1]), 0.f));
            As[(kk + 2) * KSTR + lm] = f2tf(fmaxf(fmaf(rA[j].z, scaleS[gk + 2], shiftS[gk + 2]), 0.f));
            As[(kk + 3) * KSTR + lm] = f2tf(fmaxf(fmaf(rA[j].w, scaleS[gk + 3], shiftS[gk + 3]), 0.f));
            Bs[(kk + 0) * KSTR + lm] = f2tf(rB[j].x);
            Bs[(kk + 1) * KSTR + lm] = f2tf(rB[j].y);
            Bs[(kk + 2) * KSTR + lm] = f2tf(rB[j].z);
            Bs[(kk + 3) * KSTR + lm] = f2tf(rB[j].w);
        }
        __syncthreads();
        if (kt + 32 < 512) {
            const int ktn = kt + 32;
            const float* __restrict__ Ys = (ktn + kh < 256) ? d_Y0 : d_Y1;
            #pragma unroll
            for (int j = 0; j < 4; j++) {
                rA[j] = *reinterpret_cast<const float4*>(&Ys[(row0 + lm) * 256 + ((ktn + kh + 4 * j) & 255)]);
                rB[j] = *reinterpret_cast<const float4*>(Wp + ktn + kh + 4 * j);
            }
        }
        #pragma unroll
        for (int ks = 0; ks < 4; ks++) {
            const int kb = ks * 8;
            unsigned af[4][4], bf[4][2];
            #pragma unroll
            for (int mi = 0; mi < 4; mi++) {
                const int m0 = wm * 64 + mi * 16;
                af[mi][0] = As[(kb + tq) * KSTR + m0 + r];
                af[mi][1] = As[(kb + tq) * KSTR + m0 + r + 8];
                af[mi][2] = As[(kb + tq + 4) * KSTR + m0 + r];
                af[mi][3] = As[(kb + tq + 4) * KSTR + m0 + r + 8];
            }
            #pragma unroll
            for (int ni = 0; ni < 4; ni++) {
                const int n0 = wn * 32 + ni * 8;
                bf[ni][0] = Bs[(kb + tq) * KSTR + n0 + r];
                bf[ni][1] = Bs[(kb + tq + 4) * KSTR + n0 + r];
            }
            #pragma unroll
            for (int mi = 0; mi < 4; mi++)
                #pragma unroll
                for (int ni = 0; ni < 4; ni++)
                    mma_tf32(acc[mi][ni], af[mi][0], af[mi][1], af[mi][2], af[mi][3],
                             bf[ni][0], bf[ni][1]);
        }
        s ^= 1;
    }

    // ---- epilogue: bias, 16-way wu dot, hierarchical reduce, write d_stp ----
    #pragma unroll
    for (int ni = 0; ni < 4; ni++) {
        const float2 bb = *reinterpret_cast<const float2*>(&bm[nblk * 128 + wn * 32 + ni * 8 + tq * 2]);
        #pragma unroll
        for (int mi = 0; mi < 4; mi++) {
            acc[mi][ni][0] += bb.x; acc[mi][ni][1] += bb.y;
            acc[mi][ni][2] += bb.x; acc[mi][ni][3] += bb.y;
        }
    }

    __syncthreads();  // reuse sm stage region for st partials
    float* stS = reinterpret_cast<float*>(sm);   // [4 wn][128 rows][16 h]

    #pragma unroll
    for (int h = 0; h < 16; h++) {
        float2 wv[4];
        #pragma unroll
        for (int ni = 0; ni < 4; ni++)
            wv[ni] = *reinterpret_cast<const float2*>(&wuS[h * 256 + nblk * 128 + wn * 32 + ni * 8 + tq * 2]);
        #pragma unroll
        for (int mi = 0; mi < 4; mi++) {
            float p0 = 0.f, p1 = 0.f;
            #pragma unroll
            for (int ni = 0; ni < 4; ni++) {
                p0 += acc[mi][ni][0] * wv[ni].x + acc[mi][ni][1] * wv[ni].y;
                p1 += acc[mi][ni][2] * wv[ni].x + acc[mi][ni][3] * wv[ni].y;
            }
            p0 += __shfl_xor_sync(0xffffffffu, p0, 1);
            p0 += __shfl_xor_sync(0xffffffffu, p0, 2);
            p1 += __shfl_xor_sync(0xffffffffu, p1, 1);
            p1 += __shfl_xor_sync(0xffffffffu, p1, 2);
            if (tq == 0) {
                const int rl = wm * 64 + mi * 16 + r;
                stS[wn * 2048 + rl * 16 + h]       = p0;
                stS[wn * 2048 + (rl + 8) * 16 + h] = p1;
            }
        }
    }
    __syncthreads();
    {
        const int rowl = tid >> 1;
        const int hh   = (tid & 1) * 8;
        float v[8];
        #pragma unroll
        for (int j = 0; j < 8; j++) {
            v[j] = stS[rowl * 16 + hh + j] + stS[2048 + rowl * 16 + hh + j]
                 + stS[4096 + rowl * 16 + hh + j] + stS[6144 + rowl * 16 + hh + j];
        }
        float* dst = &d_stp[nblk][(row0 + rowl) * 16 + hh];
        *reinterpret_cast<float4*>(dst)     = make_float4(v[0], v[1], v[2], v[3]);
        *reinterpret_cast<float4*>(dst + 4) = make_float4(v[4], v[5], v[6], v[7]);
    }
}

// ============================================================================
// Kernel 6: per-group softmax-weighted mean + tanh readout
// ============================================================================
__global__ void groups_kernel(float* __restrict__ out)
{
    __shared__ float sb[NPGC * 16];
    __shared__ float hv[8];
    const int g = blockIdx.x;
    const int tid = threadIdx.x;
    const float* __restrict__ b0 = &d_stp[0][g * (NPGC * 16)];
    const float* __restrict__ b1 = &d_stp[1][g * (NPGC * 16)];
    for (int i = tid; i < NPGC * 16; i += 256) sb[i] = b0[i] + b1[i];
    __syncthreads();

    const int h    = tid >> 5;
    const int lane = tid & 31;

    float mx = -1e30f;
    for (int r = lane; r < NPGC; r += 32) mx = fmaxf(mx, sb[r * 16 + h]);
    #pragma unroll
    for (int off = 16; off; off >>= 1) mx = fmaxf(mx, __shfl_xor_sync(0xffffffffu, mx, off));

    float num = 0.f, den = 0.f;
    for (int r = lane; r < NPGC; r += 32) {
        const float e = expf(sb[r * 16 + h] - mx);
        num = fmaf(e, sb[r * 16 + 8 + h], num);
        den += e;
    }
    #pragma unroll
    for (int off = 16; off; off >>= 1) {
        num += __shfl_xor_sync(0xffffffffu, num, off);
        den += __shfl_xor_sync(0xffffffffu, den, off);
    }
    if (lane == 0) hv[h] = num / den;
    __syncthreads();

    if (tid == 0) {
        float s = d_cconst[0];
        #pragma unroll
        for (int i = 0; i < 8; i++) s += hv[i];
        out[g] = tanhf(s);
    }
}

// ============================================================================
extern "C" void kernel_launch(void* const* d_in, const int* in_sizes, int n_in,
                              void* d_out, int out_size)
{
    const float* x0   = (const float*)d_in[0];
    const float* x1   = (const float*)d_in[1];
    const float* p0W  = (const float*)d_in[3];
    const float* p0b  = (const float*)d_in[4];
    const float* p0g  = (const float*)d_in[5];
    const float* p0be = (const float*)d_in[6];
    const float* p1W  = (const float*)d_in[7];
    const float* p1b  = (const float*)d_in[8];
    const float* p1g  = (const float*)d_in[9];
    const float* p1be = (const float*)d_in[10];
    const float* mW   = (const float*)d_in[11];
    const float* mb   = (const float*)d_in[12];
    const float* ipW  = (const float*)d_in[13];
    const float* ipb  = (const float*)d_in[14];
    const float* opW  = (const float*)d_in[15];
    const float* opb  = (const float*)d_in[16];
    const float* rW   = (const float*)d_in[17];
    const float* rb   = (const float*)d_in[18];
    float* out = (float*)d_out;

    cudaFuncSetAttribute(gemm1, cudaFuncAttributeMaxDynamicSharedMemorySize, SMEM1);
    cudaFuncSetAttribute(gemm2, cudaFuncAttributeMaxDynamicSharedMemorySize, SMEM2);

    prep_kernel<<<1, 256>>>(ipW, ipb, opW, opb, rW, rb);
    gemm1<<<dim3(MB, 2, 2), 256, SMEM1>>>(x0, x1, p0W, p0b, p1W, p1b);
    stats_partial<<<16, 256>>>();
    stats_final<<<2, 256>>>(p0g, p0be, p1g, p1be);
    gemm2<<<dim3(MB, 2), 256, SMEM2>>>(mW, mb);
    groups_kernel<<<NG, 256>>>(out);
}

// round 5
// speedup vs baseline: 2.6278x; 1.9655x over previous
#include <cuda_runtime.h>
#include <cuda_fp16.h>
#include <cstdint>
#include <math.h>

#define NROWS 204800
#define NG    2048
#define NPGC  100
#define MB    1600            // NROWS / 128

// ---- scratch (device globals; allocation forbidden) ----
__device__ __half d_Yh0[NROWS * 256];
__device__ __half d_Yh1[NROWS * 256];
__device__ float d_psum  [2 * MB * 256];
__device__ float d_psumsq[2 * MB * 256];
__device__ float d_psum2  [16 * 256];
__device__ float d_psumsq2[16 * 256];
__device__ float d_bnscale[512];
__device__ float d_bnshift[512];
__device__ float d_wu[16 * 256];        // rows 0..7: ws_h ; rows 8..15: u_h
__device__ float d_cconst[1];
__device__ float d_stp[2][NROWS * 16];  // per-nblk partial [scores(8)|t(8)]

// ---- helpers ----
__device__ __forceinline__ unsigned hpack(float a, float b) {
    __half2 h = __floats2half2_rn(a, b);
    return *reinterpret_cast<unsigned*>(&h);
}
__device__ __forceinline__ float2 hunpack(unsigned u) {
    return __half22float2(*reinterpret_cast<__half2*>(&u));
}
__device__ __forceinline__ void mma_f16(float c[4],
    unsigned a0, unsigned a1, unsigned a2, unsigned a3, unsigned b0, unsigned b1)
{
    asm volatile(
        "mma.sync.aligned.m16n8k16.row.col.f32.f16.f16.f32 "
        "{%0,%1,%2,%3},{%4,%5,%6,%7},{%8,%9},{%0,%1,%2,%3};"
        : "+f"(c[0]), "+f"(c[1]), "+f"(c[2]), "+f"(c[3])
        : "r"(a0), "r"(a1), "r"(a2), "r"(a3), "r"(b0), "r"(b1));
}

// smem: A stage 128 rows x 32 halfs, row stride 40 halfs (80B) = 10240 B
//       B stage same. stage = 20480 B, double buffered = 40960 B.
constexpr int RSTR   = 80;       // bytes per smem row (40 halfs)
constexpr int ASTAGE = 10240;
constexpr int STAGEB = 20480;
constexpr int SMEM1  = 2 * STAGEB;                       // 40960
constexpr int SMEM2  = 2 * STAGEB + (4096 + 1024) * 4;   // + wu + scale/shift = 61440

// ============================================================================
// Kernel 1: fold weights -> ws_h, u_h, cconst
// ============================================================================
__global__ void prep_kernel(const float* __restrict__ ipW, const float* __restrict__ ipb,
                            const float* __restrict__ opW, const float* __restrict__ opb,
                            const float* __restrict__ rW,  const float* __restrict__ rb)
{
    __shared__ float q[256];
    __shared__ float r2[256];
    __shared__ float red[256];
    const int tid = threadIdx.x;

    float s = 0.f;
    for (int k = 0; k < 256; k += 4) {
        float4 v = *reinterpret_cast<const float4*>(&ipW[tid * 256 + k]);
        s += v.x + v.y + v.z + v.w;
    }
    q[tid] = (s + ipb[tid]) * 0.17677669529663687f;

    float s2 = 0.f;
    for (int c = 0; c < 256; c++) s2 += rW[c] * opW[c * 256 + tid];
    r2[tid] = s2;
    __syncthreads();

    const int c = tid;
    for (int h = 0; h < 8; h++) {
        float a = 0.f, u = 0.f;
        #pragma unroll 8
        for (int d = 0; d < 32; d++) {
            a += q [h * 32 + d] * ipW[(256 + h * 32 + d) * 256 + c];
            u += r2[h * 32 + d] * ipW[(512 + h * 32 + d) * 256 + c];
        }
        d_wu[h * 256 + c]       = a;
        d_wu[(8 + h) * 256 + c] = u;
    }

    red[tid] = ipb[512 + tid] * r2[tid] + rW[tid] * opb[tid];
    __syncthreads();
    for (int off = 128; off; off >>= 1) {
        if (tid < off) red[tid] += red[tid + off];
        __syncthreads();
    }
    if (tid == 0) d_cconst[0] = red[0] + rb[0];
}

// ============================================================================
// Kernel 2: fp16 MMA GEMM  Y = X @ W^T + b  (half output) + column stats
// grid (MB, 2 nblk, 2 mat), 256 threads, tile 128x128, BK=32
// ============================================================================
__global__ __launch_bounds__(256, 2)
void gemm1(const float* __restrict__ X0, const float* __restrict__ X1,
           const float* __restrict__ W0, const float* __restrict__ B0,
           const float* __restrict__ W1, const float* __restrict__ B1)
{
    extern __shared__ char sm[];
    const int mat  = blockIdx.z;
    const int nblk = blockIdx.y;
    const float* __restrict__ X    = mat ? X1 : X0;
    const float* __restrict__ W    = (mat ? W1 : W0) + nblk * 128 * 256;
    const float* __restrict__ bias = (mat ? B1 : B0) + nblk * 128;

    const int tid = threadIdx.x, lane = tid & 31, wid = tid >> 5;
    const int wm = wid >> 2, wn = wid & 3;
    const int g = lane >> 2, tq = lane & 3;
    const int row0 = blockIdx.x * 128;
    const int r = tid >> 1, cg = (tid & 1) * 16;

    const float* __restrict__ Xr = X + (row0 + r) * 256;
    const float* __restrict__ Wr = W + r * 256;

    unsigned ah[8], bh[8];
    #pragma unroll
    for (int j = 0; j < 4; j++) {
        float4 a = *reinterpret_cast<const float4*>(Xr + cg + 4 * j);
        float4 b = *reinterpret_cast<const float4*>(Wr + cg + 4 * j);
        ah[2*j] = hpack(a.x, a.y); ah[2*j+1] = hpack(a.z, a.w);
        bh[2*j] = hpack(b.x, b.y); bh[2*j+1] = hpack(b.z, b.w);
    }

    float acc[4][4][4];
    #pragma unroll
    for (int mi = 0; mi < 4; mi++)
        #pragma unroll
        for (int ni = 0; ni < 4; ni++)
            #pragma unroll
            for (int e = 0; e < 4; e++) acc[mi][ni][e] = 0.f;

    #pragma unroll 1
    for (int i = 0; i < 8; i++) {
        char* As = sm + (i & 1) * STAGEB;
        char* Bs = As + ASTAGE;
        *reinterpret_cast<uint4*>(As + r * RSTR + cg * 2)      = make_uint4(ah[0], ah[1], ah[2], ah[3]);
        *reinterpret_cast<uint4*>(As + r * RSTR + cg * 2 + 16) = make_uint4(ah[4], ah[5], ah[6], ah[7]);
        *reinterpret_cast<uint4*>(Bs + r * RSTR + cg * 2)      = make_uint4(bh[0], bh[1], bh[2], bh[3]);
        *reinterpret_cast<uint4*>(Bs + r * RSTR + cg * 2 + 16) = make_uint4(bh[4], bh[5], bh[6], bh[7]);
        __syncthreads();
        if (i < 7) {
            const int kt = 32 * (i + 1);
            #pragma unroll
            for (int j = 0; j < 4; j++) {
                float4 a = *reinterpret_cast<const float4*>(Xr + kt + cg + 4 * j);
                float4 b = *reinterpret_cast<const float4*>(Wr + kt + cg + 4 * j);
                ah[2*j] = hpack(a.x, a.y); ah[2*j+1] = hpack(a.z, a.w);
                bh[2*j] = hpack(b.x, b.y); bh[2*j+1] = hpack(b.z, b.w);
            }
        }
        #pragma unroll
        for (int kc = 0; kc < 32; kc += 16) {
            const char* Ab = As + (wm * 64) * RSTR + (kc + 2 * tq) * 2;
            const char* Bb = Bs + (wn * 32) * RSTR + (kc + 2 * tq) * 2;
            unsigned af[4][4], bf[4][2];
            #pragma unroll
            for (int mi = 0; mi < 4; mi++) {
                const char* p = Ab + (mi * 16 + g) * RSTR;
                af[mi][0] = *reinterpret_cast<const unsigned*>(p);
                af[mi][1] = *reinterpret_cast<const unsigned*>(p + 8 * RSTR);
                af[mi][2] = *reinterpret_cast<const unsigned*>(p + 16);
                af[mi][3] = *reinterpret_cast<const unsigned*>(p + 8 * RSTR + 16);
            }
            #pragma unroll
            for (int ni = 0; ni < 4; ni++) {
                const char* p = Bb + (ni * 8 + g) * RSTR;
                bf[ni][0] = *reinterpret_cast<const unsigned*>(p);
                bf[ni][1] = *reinterpret_cast<const unsigned*>(p + 16);
            }
            #pragma unroll
            for (int mi = 0; mi < 4; mi++)
                #pragma unroll
                for (int ni = 0; ni < 4; ni++)
                    mma_f16(acc[mi][ni], af[mi][0], af[mi][1], af[mi][2], af[mi][3],
                            bf[ni][0], bf[ni][1]);
        }
    }

    // ---- epilogue: bias, write Y (half), column stats ----
    float2 bb[4];
    #pragma unroll
    for (int ni = 0; ni < 4; ni++)
        bb[ni] = *reinterpret_cast<const float2*>(&bias[wn * 32 + ni * 8 + tq * 2]);
    #pragma unroll
    for (int mi = 0; mi < 4; mi++)
        #pragma unroll
        for (int ni = 0; ni < 4; ni++) {
            acc[mi][ni][0] += bb[ni].x; acc[mi][ni][1] += bb[ni].y;
            acc[mi][ni][2] += bb[ni].x; acc[mi][ni][3] += bb[ni].y;
        }

    __half* __restrict__ Y = mat ? d_Yh1 : d_Yh0;
    const int colbase = nblk * 128 + wn * 32;
    #pragma unroll
    for (int mi = 0; mi < 4; mi++) {
        const int R0 = row0 + wm * 64 + mi * 16 + g;
        #pragma unroll
        for (int ni = 0; ni < 4; ni++) {
            const int gc = colbase + ni * 8 + tq * 2;
            *reinterpret_cast<unsigned*>(&Y[R0 * 256 + gc])       = hpack(acc[mi][ni][0], acc[mi][ni][1]);
            *reinterpret_cast<unsigned*>(&Y[(R0 + 8) * 256 + gc]) = hpack(acc[mi][ni][2], acc[mi][ni][3]);
        }
    }

    __syncthreads();   // safe to reuse sm
    float* ssum = reinterpret_cast<float*>(sm);       // [2][128]
    float* ssq  = ssum + 256;
    #pragma unroll
    for (int ni = 0; ni < 4; ni++) {
        float s0 = 0.f, s1 = 0.f, q0 = 0.f, q1 = 0.f;
        #pragma unroll
        for (int mi = 0; mi < 4; mi++) {
            const float v0 = acc[mi][ni][0], v1 = acc[mi][ni][1];
            const float v2 = acc[mi][ni][2], v3 = acc[mi][ni][3];
            s0 += v0 + v2; s1 += v1 + v3;
            q0 += v0 * v0 + v2 * v2; q1 += v1 * v1 + v3 * v3;
        }
        #pragma unroll
        for (int off = 4; off < 32; off <<= 1) {
            s0 += __shfl_xor_sync(0xffffffffu, s0, off);
            s1 += __shfl_xor_sync(0xffffffffu, s1, off);
            q0 += __shfl_xor_sync(0xffffffffu, q0, off);
            q1 += __shfl_xor_sync(0xffffffffu, q1, off);
        }
        if (lane < 4) {
            const int lcol = wn * 32 + ni * 8 + tq * 2;
            ssum[wm * 128 + lcol] = s0;  ssum[wm * 128 + lcol + 1] = s1;
            ssq [wm * 128 + lcol] = q0;  ssq [wm * 128 + lcol + 1] = q1;
        }
    }
    __syncthreads();
    if (tid < 128) {
        const int gidx = (mat * MB + blockIdx.x) * 256 + nblk * 128 + tid;
        d_psum  [gidx] = ssum[tid] + ssum[128 + tid];
        d_psumsq[gidx] = ssq [tid] + ssq [128 + tid];
    }
}

// ============================================================================
// Kernels 3/4: deterministic stat reduction -> BN scale/shift
// ============================================================================
__global__ void stats_partial()
{
    const int mat = blockIdx.x >> 3;
    const int sl  = blockIdx.x & 7;
    const int col = threadIdx.x;
    float s = 0.f, q = 0.f;
    const int rb0 = sl * (MB / 8);
    for (int rbi = rb0; rbi < rb0 + (MB / 8); rbi++) {
        s += d_psum  [(mat * MB + rbi) * 256 + col];
        q += d_psumsq[(mat * MB + rbi) * 256 + col];
    }
    d_psum2  [blockIdx.x * 256 + col] = s;
    d_psumsq2[blockIdx.x * 256 + col] = q;
}

__global__ void stats_final(const float* __restrict__ g0, const float* __restrict__ be0,
                            const float* __restrict__ g1, const float* __restrict__ be1)
{
    const int mat = blockIdx.x;
    const int col = threadIdx.x;
    float s = 0.f, q = 0.f;
    #pragma unroll
    for (int sl = 0; sl < 8; sl++) {
        s += d_psum2  [(mat * 8 + sl) * 256 + col];
        q += d_psumsq2[(mat * 8 + sl) * 256 + col];
    }
    const float inv  = 1.0f / (float)NROWS;
    const float mean = s * inv;
    const float var  = fmaxf(q * inv - mean * mean, 0.f);
    const float* gg = mat ? g1 : g0;
    const float* bb = mat ? be1 : be0;
    const float sc = gg[col] * rsqrtf(var + 1e-5f);
    d_bnscale[mat * 256 + col] = sc;
    d_bnshift[mat * 256 + col] = bb[col] - mean * sc;
}

// ============================================================================
// Kernel 5: fp16 MMA merge GEMM (BN+ReLU fused on A) + scores/t epilogue
// grid (MB, 2 nblk), 256 threads, K=512 (16 chunks of 32)
// ============================================================================
__global__ __launch_bounds__(256, 2)
void gemm2(const float* __restrict__ Wm, const float* __restrict__ bm)
{
    extern __shared__ char sm[];
    float* wuS = reinterpret_cast<float*>(sm + 2 * STAGEB);   // [16][256]
    float* sS  = wuS + 4096;                                   // [512]
    float* hS  = sS + 512;                                     // [512]

    const int nblk = blockIdx.y;
    const int tid = threadIdx.x, lane = tid & 31, wid = tid >> 5;
    const int wm = wid >> 2, wn = wid & 3;
    const int g = lane >> 2, tq = lane & 3;
    const int row0 = blockIdx.x * 128;
    const int r = tid >> 1, cg = (tid & 1) * 16;

    for (int i = tid; i < 4096; i += 256) wuS[i] = d_wu[i];
    for (int i = tid; i < 512; i += 256) { sS[i] = d_bnscale[i]; hS[i] = d_bnshift[i]; }
    __syncthreads();

    const float* __restrict__ Wr = Wm + (nblk * 128 + r) * 512;

    uint4 ya, yb;            // 16 halfs of Y for this thread's (row, k-chunk)
    unsigned bh[8];
    {
        const __half* __restrict__ Ys = (cg < 256) ? d_Yh0 : d_Yh1;
        ya = *reinterpret_cast<const uint4*>(&Ys[(row0 + r) * 256 + (cg & 255)]);
        yb = *reinterpret_cast<const uint4*>(&Ys[(row0 + r) * 256 + (cg & 255) + 8]);
        #pragma unroll
        for (int j = 0; j < 4; j++) {
            float4 b = *reinterpret_cast<const float4*>(Wr + cg + 4 * j);
            bh[2*j] = hpack(b.x, b.y); bh[2*j+1] = hpack(b.z, b.w);
        }
    }

    float acc[4][4][4];
    #pragma unroll
    for (int mi = 0; mi < 4; mi++)
        #pragma unroll
        for (int ni = 0; ni < 4; ni++)
            #pragma unroll
            for (int e = 0; e < 4; e++) acc[mi][ni][e] = 0.f;

    #pragma unroll 1
    for (int i = 0; i < 16; i++) {
        char* As = sm + (i & 1) * STAGEB;
        char* Bs = As + ASTAGE;
        const int kt = 32 * i;
        {
            const unsigned yw[8] = {ya.x, ya.y, ya.z, ya.w, yb.x, yb.y, yb.z, yb.w};
            unsigned aw[8];
            #pragma unroll
            for (int e = 0; e < 8; e++) {
                const int gk = kt + cg + 2 * e;
                float2 f = hunpack(yw[e]);
                f.x = fmaxf(fmaf(f.x, sS[gk + 0], hS[gk + 0]), 0.f);
                f.y = fmaxf(fmaf(f.y, sS[gk + 1], hS[gk + 1]), 0.f);
                aw[e] = hpack(f.x, f.y);
            }
            *reinterpret_cast<uint4*>(As + r * RSTR + cg * 2)      = make_uint4(aw[0], aw[1], aw[2], aw[3]);
            *reinterpret_cast<uint4*>(As + r * RSTR + cg * 2 + 16) = make_uint4(aw[4], aw[5], aw[6], aw[7]);
            *reinterpret_cast<uint4*>(Bs + r * RSTR + cg * 2)      = make_uint4(bh[0], bh[1], bh[2], bh[3]);
            *reinterpret_cast<uint4*>(Bs + r * RSTR + cg * 2 + 16) = make_uint4(bh[4], bh[5], bh[6], bh[7]);
        }
        __syncthreads();
        if (i < 15) {
            const int ktn = kt + 32;
            const int gk0 = ktn + cg;
            const __half* __restrict__ Ys = (gk0 < 256) ? d_Yh0 : d_Yh1;
            ya = *reinterpret_cast<const uint4*>(&Ys[(row0 + r) * 256 + (gk0 & 255)]);
            yb = *reinterpret_cast<const uint4*>(&Ys[(row0 + r) * 256 + (gk0 & 255) + 8]);
            #pragma unroll
            for (int j = 0; j < 4; j++) {
                float4 b = *reinterpret_cast<const float4*>(Wr + ktn + cg + 4 * j);
                bh[2*j] = hpack(b.x, b.y); bh[2*j+1] = hpack(b.z, b.w);
            }
        }
        #pragma unroll
        for (int kc = 0; kc < 32; kc += 16) {
            const char* Ab = As + (wm * 64) * RSTR + (kc + 2 * tq) * 2;
            const char* Bb = Bs + (wn * 32) * RSTR + (kc + 2 * tq) * 2;
            unsigned af[4][4], bf[4][2];
            #pragma unroll
            for (int mi = 0; mi < 4; mi++) {
                const char* p = Ab + (mi * 16 + g) * RSTR;
                af[mi][0] = *reinterpret_cast<const unsigned*>(p);
                af[mi][1] = *reinterpret_cast<const unsigned*>(p + 8 * RSTR);
                af[mi][2] = *reinterpret_cast<const unsigned*>(p + 16);
                af[mi][3] = *reinterpret_cast<const unsigned*>(p + 8 * RSTR + 16);
            }
            #pragma unroll
            for (int ni = 0; ni < 4; ni++) {
                const char* p = Bb + (ni * 8 + g) * RSTR;
                bf[ni][0] = *reinterpret_cast<const unsigned*>(p);
                bf[ni][1] = *reinterpret_cast<const unsigned*>(p + 16);
            }
            #pragma unroll
            for (int mi = 0; mi < 4; mi++)
                #pragma unroll
                for (int ni = 0; ni < 4; ni++)
                    mma_f16(acc[mi][ni], af[mi][0], af[mi][1], af[mi][2], af[mi][3],
                            bf[ni][0], bf[ni][1]);
        }
    }

    // ---- epilogue: bias, 16-way wu dot, hierarchical reduce, write d_stp ----
    #pragma unroll
    for (int ni = 0; ni < 4; ni++) {
        const float2 bb = *reinterpret_cast<const float2*>(&bm[nblk * 128 + wn * 32 + ni * 8 + tq * 2]);
        #pragma unroll
        for (int mi = 0; mi < 4; mi++) {
            acc[mi][ni][0] += bb.x; acc[mi][ni][1] += bb.y;
            acc[mi][ni][2] += bb.x; acc[mi][ni][3] += bb.y;
        }
    }

    __syncthreads();  // reuse stage region for st partials
    float* stS = reinterpret_cast<float*>(sm);   // [4 wn][128 rows][16 h]

    #pragma unroll
    for (int h = 0; h < 16; h++) {
        float2 wv[4];
        #pragma unroll
        for (int ni = 0; ni < 4; ni++)
            wv[ni] = *reinterpret_cast<const float2*>(&wuS[h * 256 + nblk * 128 + wn * 32 + ni * 8 + tq * 2]);
        #pragma unroll
        for (int mi = 0; mi < 4; mi++) {
            float p0 = 0.f, p1 = 0.f;
            #pragma unroll
            for (int ni = 0; ni < 4; ni++) {
                p0 += acc[mi][ni][0] * wv[ni].x + acc[mi][ni][1] * wv[ni].y;
                p1 += acc[mi][ni][2] * wv[ni].x + acc[mi][ni][3] * wv[ni].y;
            }
            p0 += __shfl_xor_sync(0xffffffffu, p0, 1);
            p0 += __shfl_xor_sync(0xffffffffu, p0, 2);
            p1 += __shfl_xor_sync(0xffffffffu, p1, 1);
            p1 += __shfl_xor_sync(0xffffffffu, p1, 2);
            if (tq == 0) {
                const int rl = wm * 64 + mi * 16 + g;
                stS[wn * 2048 + rl * 16 + h]       = p0;
                stS[wn * 2048 + (rl + 8) * 16 + h] = p1;
            }
        }
    }
    __syncthreads();
    {
        const int rowl = tid >> 1, hh = (tid & 1) * 8;
        float v[8];
        #pragma unroll
        for (int j = 0; j < 8; j++) {
            v[j] = stS[rowl * 16 + hh + j] + stS[2048 + rowl * 16 + hh + j]
                 + stS[4096 + rowl * 16 + hh + j] + stS[6144 + rowl * 16 + hh + j];
        }
        float* dst = &d_stp[nblk][(row0 + rowl) * 16 + hh];
        *reinterpret_cast<float4*>(dst)     = make_float4(v[0], v[1], v[2], v[3]);
        *reinterpret_cast<float4*>(dst + 4) = make_float4(v[4], v[5], v[6], v[7]);
    }
}

// ============================================================================
// Kernel 6: per-group softmax-weighted mean + tanh readout
// ============================================================================
__global__ void groups_kernel(float* __restrict__ out)
{
    __shared__ float sb[NPGC * 16];
    __shared__ float hv[8];
    const int g = blockIdx.x;
    const int tid = threadIdx.x;
    const float* __restrict__ b0 = &d_stp[0][g * (NPGC * 16)];
    const float* __restrict__ b1 = &d_stp[1][g * (NPGC * 16)];
    for (int i = tid; i < NPGC * 16; i += 256) sb[i] = b0[i] + b1[i];
    __syncthreads();

    const int h    = tid >> 5;
    const int lane = tid & 31;

    float mx = -1e30f;
    for (int r = lane; r < NPGC; r += 32) mx = fmaxf(mx, sb[r * 16 + h]);
    #pragma unroll
    for (int off = 16; off; off >>= 1) mx = fmaxf(mx, __shfl_xor_sync(0xffffffffu, mx, off));

    float num = 0.f, den = 0.f;
    for (int r = lane; r < NPGC; r += 32) {
        const float e = expf(sb[r * 16 + h] - mx);
        num = fmaf(e, sb[r * 16 + 8 + h], num);
        den += e;
    }
    #pragma unroll
    for (int off = 16; off; off >>= 1) {
        num += __shfl_xor_sync(0xffffffffu, num, off);
        den += __shfl_xor_sync(0xffffffffu, den, off);
    }
    if (lane == 0) hv[h] = num / den;
    __syncthreads();

    if (tid == 0) {
        float s = d_cconst[0];
        #pragma unroll
        for (int i = 0; i < 8; i++) s += hv[i];
        out[g] = tanhf(s);
    }
}

// ============================================================================
extern "C" void kernel_launch(void* const* d_in, const int* in_sizes, int n_in,
                              void* d_out, int out_size)
{
    const float* x0   = (const float*)d_in[0];
    const float* x1   = (const float*)d_in[1];
    const float* p0W  = (const float*)d_in[3];
    const float* p0b  = (const float*)d_in[4];
    const float* p0g  = (const float*)d_in[5];
    const float* p0be = (const float*)d_in[6];
    const float* p1W  = (const float*)d_in[7];
    const float* p1b  = (const float*)d_in[8];
    const float* p1g  = (const float*)d_in[9];
    const float* p1be = (const float*)d_in[10];
    const float* mW   = (const float*)d_in[11];
    const float* mb   = (const float*)d_in[12];
    const float* ipW  = (const float*)d_in[13];
    const float* ipb  = (const float*)d_in[14];
    const float* opW  = (const float*)d_in[15];
    const float* opb  = (const float*)d_in[16];
    const float* rW   = (const float*)d_in[17];
    const float* rb   = (const float*)d_in[18];
    float* out = (float*)d_out;

    cudaFuncSetAttribute(gemm1, cudaFuncAttributeMaxDynamicSharedMemorySize, SMEM1);
    cudaFuncSetAttribute(gemm2, cudaFuncAttributeMaxDynamicSharedMemorySize, SMEM2);

    prep_kernel<<<1, 256>>>(ipW, ipb, opW, opb, rW, rb);
    gemm1<<<dim3(MB, 2, 2), 256, SMEM1>>>(x0, x1, p0W, p0b, p1W, p1b);
    stats_partial<<<16, 256>>>();
    stats_final<<<2, 256>>>(p0g, p0be, p1g, p1be);
    gemm2<<<dim3(MB, 2), 256, SMEM2>>>(mW, mb);
    groups_kernel<<<NG, 256>>>(out);
}

// round 6
// speedup vs baseline: 2.7802x; 1.0580x over previous
#include <cuda_runtime.h>
#include <cuda_fp16.h>
#include <cstdint>
#include <math.h>

#define NROWS 204800
#define NG    2048
#define NPGC  100
#define MB    1600            // NROWS / 128

// ---- scratch (device globals; allocation forbidden) ----
__device__ __half d_Yh0[NROWS * 256];
__device__ __half d_Yh1[NROWS * 256];
__device__ float d_psum  [2 * MB * 256];
__device__ float d_psumsq[2 * MB * 256];
__device__ float d_psum2  [16 * 256];
__device__ float d_psumsq2[16 * 256];
__device__ float d_bnscale[512];
__device__ float d_bnshift[512];
__device__ float d_wu[16 * 256];        // rows 0..7: ws_h ; rows 8..15: u_h
__device__ float d_cconst[1];
__device__ float d_stp[2][NROWS * 16];  // per-nblk partial [scores(8)|t(8)]

// ---- helpers ----
__device__ __forceinline__ unsigned hpack(float a, float b) {
    __half2 h = __floats2half2_rn(a, b);
    return *reinterpret_cast<unsigned*>(&h);
}
__device__ __forceinline__ float2 hunpack(unsigned u) {
    return __half22float2(*reinterpret_cast<__half2*>(&u));
}
__device__ __forceinline__ void mma_f16(float c[4],
    unsigned a0, unsigned a1, unsigned a2, unsigned a3, unsigned b0, unsigned b1)
{
    asm volatile(
        "mma.sync.aligned.m16n8k16.row.col.f32.f16.f16.f32 "
        "{%0,%1,%2,%3},{%4,%5,%6,%7},{%8,%9},{%0,%1,%2,%3};"
        : "+f"(c[0]), "+f"(c[1]), "+f"(c[2]), "+f"(c[3])
        : "r"(a0), "r"(a1), "r"(a2), "r"(a3), "r"(b0), "r"(b1));
}
__device__ __forceinline__ void ldsm4(unsigned& r0, unsigned& r1, unsigned& r2, unsigned& r3,
                                      uint32_t addr)
{
    asm volatile("ldmatrix.sync.aligned.m8n8.x4.shared.b16 {%0,%1,%2,%3}, [%4];"
        : "=r"(r0), "=r"(r1), "=r"(r2), "=r"(r3) : "r"(addr));
}

// smem: A stage 128 rows x 32 halfs, row stride 40 halfs (80B) = 10240 B
//       B stage same. stage = 20480 B, double buffered = 40960 B.
constexpr int RSTR   = 80;       // bytes per smem row (40 halfs)
constexpr int ASTAGE = 10240;
constexpr int STAGEB = 20480;
constexpr int SMEM1  = 2 * STAGEB;                       // 40960
constexpr int SMEM2  = 2 * STAGEB + (4096 + 1024) * 4;   // + wu + scale/shift = 61440

// ============================================================================
// Kernel 1: fold weights -> ws_h, u_h, cconst
// ============================================================================
__global__ void prep_kernel(const float* __restrict__ ipW, const float* __restrict__ ipb,
                            const float* __restrict__ opW, const float* __restrict__ opb,
                            const float* __restrict__ rW,  const float* __restrict__ rb)
{
    __shared__ float q[256];
    __shared__ float r2[256];
    __shared__ float red[256];
    const int tid = threadIdx.x;

    float s = 0.f;
    for (int k = 0; k < 256; k += 4) {
        float4 v = *reinterpret_cast<const float4*>(&ipW[tid * 256 + k]);
        s += v.x + v.y + v.z + v.w;
    }
    q[tid] = (s + ipb[tid]) * 0.17677669529663687f;

    float s2 = 0.f;
    for (int c = 0; c < 256; c++) s2 += rW[c] * opW[c * 256 + tid];
    r2[tid] = s2;
    __syncthreads();

    const int c = tid;
    for (int h = 0; h < 8; h++) {
        float a = 0.f, u = 0.f;
        #pragma unroll 8
        for (int d = 0; d < 32; d++) {
            a += q [h * 32 + d] * ipW[(256 + h * 32 + d) * 256 + c];
            u += r2[h * 32 + d] * ipW[(512 + h * 32 + d) * 256 + c];
        }
        d_wu[h * 256 + c]       = a;
        d_wu[(8 + h) * 256 + c] = u;
    }

    red[tid] = ipb[512 + tid] * r2[tid] + rW[tid] * opb[tid];
    __syncthreads();
    for (int off = 128; off; off >>= 1) {
        if (tid < off) red[tid] += red[tid + off];
        __syncthreads();
    }
    if (tid == 0) d_cconst[0] = red[0] + rb[0];
}

// ============================================================================
// Kernel 2: fp16 MMA GEMM  Y = X @ W^T + b  (half output) + column stats
// grid (MB, 2 nblk, 2 mat), 256 threads, tile 128x128, BK=32, ldmatrix frags
// ============================================================================
__global__ __launch_bounds__(256, 2)
void gemm1(const float* __restrict__ X0, const float* __restrict__ X1,
           const float* __restrict__ W0, const float* __restrict__ B0,
           const float* __restrict__ W1, const float* __restrict__ B1)
{
    extern __shared__ char sm[];
    const uint32_t sa = (uint32_t)__cvta_generic_to_shared(sm);

    const int mat  = blockIdx.z;
    const int nblk = blockIdx.y;
    const float* __restrict__ X    = mat ? X1 : X0;
    const float* __restrict__ W    = (mat ? W1 : W0) + nblk * 128 * 256;
    const float* __restrict__ bias = (mat ? B1 : B0) + nblk * 128;

    const int tid = threadIdx.x, lane = tid & 31, wid = tid >> 5;
    const int wm = wid >> 2, wn = wid & 3;
    const int g = lane >> 2, tq = lane & 3;
    const int row0 = blockIdx.x * 128;
    const int r = tid >> 1, cg = (tid & 1) * 16;

    // ldmatrix per-lane base offsets (within a stage)
    const uint32_t aOff = (uint32_t)((wm * 64 + (lane & 15)) * RSTR + ((lane >> 4) * 8) * 2);
    const uint32_t bOff = (uint32_t)(ASTAGE
                        + (wn * 32 + (lane & 7) + ((lane >> 4) << 3)) * RSTR
                        + (((lane >> 3) & 1) * 8) * 2);

    const float* __restrict__ Xr = X + (row0 + r) * 256;
    const float* __restrict__ Wr = W + r * 256;

    unsigned ah[8], bh[8];
    #pragma unroll
    for (int j = 0; j < 4; j++) {
        float4 a = *reinterpret_cast<const float4*>(Xr + cg + 4 * j);
        float4 b = *reinterpret_cast<const float4*>(Wr + cg + 4 * j);
        ah[2*j] = hpack(a.x, a.y); ah[2*j+1] = hpack(a.z, a.w);
        bh[2*j] = hpack(b.x, b.y); bh[2*j+1] = hpack(b.z, b.w);
    }

    float acc[4][4][4];
    #pragma unroll
    for (int mi = 0; mi < 4; mi++)
        #pragma unroll
        for (int ni = 0; ni < 4; ni++)
            #pragma unroll
            for (int e = 0; e < 4; e++) acc[mi][ni][e] = 0.f;

    #pragma unroll 1
    for (int i = 0; i < 8; i++) {
        char* As = sm + (i & 1) * STAGEB;
        char* Bs = As + ASTAGE;
        const uint32_t stg = sa + (i & 1) * STAGEB;
        *reinterpret_cast<uint4*>(As + r * RSTR + cg * 2)      = make_uint4(ah[0], ah[1], ah[2], ah[3]);
        *reinterpret_cast<uint4*>(As + r * RSTR + cg * 2 + 16) = make_uint4(ah[4], ah[5], ah[6], ah[7]);
        *reinterpret_cast<uint4*>(Bs + r * RSTR + cg * 2)      = make_uint4(bh[0], bh[1], bh[2], bh[3]);
        *reinterpret_cast<uint4*>(Bs + r * RSTR + cg * 2 + 16) = make_uint4(bh[4], bh[5], bh[6], bh[7]);
        __syncthreads();
        if (i < 7) {
            const int kt = 32 * (i + 1);
            #pragma unroll
            for (int j = 0; j < 4; j++) {
                float4 a = *reinterpret_cast<const float4*>(Xr + kt + cg + 4 * j);
                float4 b = *reinterpret_cast<const float4*>(Wr + kt + cg + 4 * j);
                ah[2*j] = hpack(a.x, a.y); ah[2*j+1] = hpack(a.z, a.w);
                bh[2*j] = hpack(b.x, b.y); bh[2*j+1] = hpack(b.z, b.w);
            }
        }
        #pragma unroll
        for (int kc = 0; kc < 32; kc += 16) {
            unsigned af[4][4], bf[4][2];
            #pragma unroll
            for (int mi = 0; mi < 4; mi++)
                ldsm4(af[mi][0], af[mi][1], af[mi][2], af[mi][3],
                      stg + aOff + mi * 16 * RSTR + kc * 2);
            ldsm4(bf[0][0], bf[0][1], bf[1][0], bf[1][1], stg + bOff + kc * 2);
            ldsm4(bf[2][0], bf[2][1], bf[3][0], bf[3][1], stg + bOff + 16 * RSTR + kc * 2);
            #pragma unroll
            for (int mi = 0; mi < 4; mi++)
                #pragma unroll
                for (int ni = 0; ni < 4; ni++)
                    mma_f16(acc[mi][ni], af[mi][0], af[mi][1], af[mi][2], af[mi][3],
                            bf[ni][0], bf[ni][1]);
        }
    }

    // ---- epilogue: bias, write Y (half), column stats ----
    float2 bb[4];
    #pragma unroll
    for (int ni = 0; ni < 4; ni++)
        bb[ni] = *reinterpret_cast<const float2*>(&bias[wn * 32 + ni * 8 + tq * 2]);
    #pragma unroll
    for (int mi = 0; mi < 4; mi++)
        #pragma unroll
        for (int ni = 0; ni < 4; ni++) {
            acc[mi][ni][0] += bb[ni].x; acc[mi][ni][1] += bb[ni].y;
            acc[mi][ni][2] += bb[ni].x; acc[mi][ni][3] += bb[ni].y;
        }

    __half* __restrict__ Y = mat ? d_Yh1 : d_Yh0;
    const int colbase = nblk * 128 + wn * 32;
    #pragma unroll
    for (int mi = 0; mi < 4; mi++) {
        const int R0 = row0 + wm * 64 + mi * 16 + g;
        #pragma unroll
        for (int ni = 0; ni < 4; ni++) {
            const int gc = colbase + ni * 8 + tq * 2;
            *reinterpret_cast<unsigned*>(&Y[R0 * 256 + gc])       = hpack(acc[mi][ni][0], acc[mi][ni][1]);
            *reinterpret_cast<unsigned*>(&Y[(R0 + 8) * 256 + gc]) = hpack(acc[mi][ni][2], acc[mi][ni][3]);
        }
    }

    __syncthreads();   // safe to reuse sm
    float* ssum = reinterpret_cast<float*>(sm);       // [2][128]
    float* ssq  = ssum + 256;
    #pragma unroll
    for (int ni = 0; ni < 4; ni++) {
        float s0 = 0.f, s1 = 0.f, q0 = 0.f, q1 = 0.f;
        #pragma unroll
        for (int mi = 0; mi < 4; mi++) {
            const float v0 = acc[mi][ni][0], v1 = acc[mi][ni][1];
            const float v2 = acc[mi][ni][2], v3 = acc[mi][ni][3];
            s0 += v0 + v2; s1 += v1 + v3;
            q0 += v0 * v0 + v2 * v2; q1 += v1 * v1 + v3 * v3;
        }
        #pragma unroll
        for (int off = 4; off < 32; off <<= 1) {
            s0 += __shfl_xor_sync(0xffffffffu, s0, off);
            s1 += __shfl_xor_sync(0xffffffffu, s1, off);
            q0 += __shfl_xor_sync(0xffffffffu, q0, off);
            q1 += __shfl_xor_sync(0xffffffffu, q1, off);
        }
        if (lane < 4) {
            const int lcol = wn * 32 + ni * 8 + tq * 2;
            ssum[wm * 128 + lcol] = s0;  ssum[wm * 128 + lcol + 1] = s1;
            ssq [wm * 128 + lcol] = q0;  ssq [wm * 128 + lcol + 1] = q1;
        }
    }
    __syncthreads();
    if (tid < 128) {
        const int gidx = (mat * MB + blockIdx.x) * 256 + nblk * 128 + tid;
        d_psum  [gidx] = ssum[tid] + ssum[128 + tid];
        d_psumsq[gidx] = ssq [tid] + ssq [128 + tid];
    }
}

// ============================================================================
// Kernels 3/4: deterministic stat reduction -> BN scale/shift
// ============================================================================
__global__ void stats_partial()
{
    const int mat = blockIdx.x >> 3;
    const int sl  = blockIdx.x & 7;
    const int col = threadIdx.x;
    float s = 0.f, q = 0.f;
    const int rb0 = sl * (MB / 8);
    for (int rbi = rb0; rbi < rb0 + (MB / 8); rbi++) {
        s += d_psum  [(mat * MB + rbi) * 256 + col];
        q += d_psumsq[(mat * MB + rbi) * 256 + col];
    }
    d_psum2  [blockIdx.x * 256 + col] = s;
    d_psumsq2[blockIdx.x * 256 + col] = q;
}

__global__ void stats_final(const float* __restrict__ g0, const float* __restrict__ be0,
                            const float* __restrict__ g1, const float* __restrict__ be1)
{
    const int mat = blockIdx.x;
    const int col = threadIdx.x;
    float s = 0.f, q = 0.f;
    #pragma unroll
    for (int sl = 0; sl < 8; sl++) {
        s += d_psum2  [(mat * 8 + sl) * 256 + col];
        q += d_psumsq2[(mat * 8 + sl) * 256 + col];
    }
    const float inv  = 1.0f / (float)NROWS;
    const float mean = s * inv;
    const float var  = fmaxf(q * inv - mean * mean, 0.f);
    const float* gg = mat ? g1 : g0;
    const float* bb = mat ? be1 : be0;
    const float sc = gg[col] * rsqrtf(var + 1e-5f);
    d_bnscale[mat * 256 + col] = sc;
    d_bnshift[mat * 256 + col] = bb[col] - mean * sc;
}

// ============================================================================
// Kernel 5: fp16 MMA merge GEMM (BN+ReLU fused on A) + scores/t epilogue
// grid (MB, 2 nblk), 256 threads, K=512 (16 chunks of 32), ldmatrix frags
// ============================================================================
__global__ __launch_bounds__(256, 2)
void gemm2(const float* __restrict__ Wm, const float* __restrict__ bm)
{
    extern __shared__ char sm[];
    const uint32_t sa = (uint32_t)__cvta_generic_to_shared(sm);
    float* wuS = reinterpret_cast<float*>(sm + 2 * STAGEB);   // [16][256]
    float* sS  = wuS + 4096;                                   // [512]
    float* hS  = sS + 512;                                     // [512]

    const int nblk = blockIdx.y;
    const int tid = threadIdx.x, lane = tid & 31, wid = tid >> 5;
    const int wm = wid >> 2, wn = wid & 3;
    const int g = lane >> 2, tq = lane & 3;
    const int row0 = blockIdx.x * 128;
    const int r = tid >> 1, cg = (tid & 1) * 16;

    const uint32_t aOff = (uint32_t)((wm * 64 + (lane & 15)) * RSTR + ((lane >> 4) * 8) * 2);
    const uint32_t bOff = (uint32_t)(ASTAGE
                        + (wn * 32 + (lane & 7) + ((lane >> 4) << 3)) * RSTR
                        + (((lane >> 3) & 1) * 8) * 2);

    for (int i = tid; i < 4096; i += 256) wuS[i] = d_wu[i];
    for (int i = tid; i < 512; i += 256) { sS[i] = d_bnscale[i]; hS[i] = d_bnshift[i]; }
    __syncthreads();

    const float* __restrict__ Wr = Wm + (nblk * 128 + r) * 512;

    uint4 ya, yb;            // 16 halfs of Y for this thread's (row, k-chunk)
    unsigned bh[8];
    {
        const __half* __restrict__ Ys = (cg < 256) ? d_Yh0 : d_Yh1;
        ya = *reinterpret_cast<const uint4*>(&Ys[(row0 + r) * 256 + (cg & 255)]);
        yb = *reinterpret_cast<const uint4*>(&Ys[(row0 + r) * 256 + (cg & 255) + 8]);
        #pragma unroll
        for (int j = 0; j < 4; j++) {
            float4 b = *reinterpret_cast<const float4*>(Wr + cg + 4 * j);
            bh[2*j] = hpack(b.x, b.y); bh[2*j+1] = hpack(b.z, b.w);
        }
    }

    float acc[4][4][4];
    #pragma unroll
    for (int mi = 0; mi < 4; mi++)
        #pragma unroll
        for (int ni = 0; ni < 4; ni++)
            #pragma unroll
            for (int e = 0; e < 4; e++) acc[mi][ni][e] = 0.f;

    #pragma unroll 1
    for (int i = 0; i < 16; i++) {
        char* As = sm + (i & 1) * STAGEB;
        char* Bs = As + ASTAGE;
        const uint32_t stg = sa + (i & 1) * STAGEB;
        const int kt = 32 * i;
        {
            const unsigned yw[8] = {ya.x, ya.y, ya.z, ya.w, yb.x, yb.y, yb.z, yb.w};
            unsigned aw[8];
            #pragma unroll
            for (int e = 0; e < 8; e++) {
                const int gk = kt + cg + 2 * e;
                float2 f = hunpack(yw[e]);
                f.x = fmaxf(fmaf(f.x, sS[gk + 0], hS[gk + 0]), 0.f);
                f.y = fmaxf(fmaf(f.y, sS[gk + 1], hS[gk + 1]), 0.f);
                aw[e] = hpack(f.x, f.y);
            }
            *reinterpret_cast<uint4*>(As + r * RSTR + cg * 2)      = make_uint4(aw[0], aw[1], aw[2], aw[3]);
            *reinterpret_cast<uint4*>(As + r * RSTR + cg * 2 + 16) = make_uint4(aw[4], aw[5], aw[6], aw[7]);
            *reinterpret_cast<uint4*>(Bs + r * RSTR + cg * 2)      = make_uint4(bh[0], bh[1], bh[2], bh[3]);
            *reinterpret_cast<uint4*>(Bs + r * RSTR + cg * 2 + 16) = make_uint4(bh[4], bh[5], bh[6], bh[7]);
        }
        __syncthreads();
        if (i < 15) {
            const int ktn = kt + 32;
            const int gk0 = ktn + cg;
            const __half* __restrict__ Ys = (gk0 < 256) ? d_Yh0 : d_Yh1;
            ya = *reinterpret_cast<const uint4*>(&Ys[(row0 + r) * 256 + (gk0 & 255)]);
            yb = *reinterpret_cast<const uint4*>(&Ys[(row0 + r) * 256 + (gk0 & 255) + 8]);
            #pragma unroll
            for (int j = 0; j < 4; j++) {
                float4 b = *reinterpret_cast<const float4*>(Wr + ktn + cg + 4 * j);
                bh[2*j] = hpack(b.x, b.y); bh[2*j+1] = hpack(b.z, b.w);
            }
        }
        #pragma unroll
        for (int kc = 0; kc < 32; kc += 16) {
            unsigned af[4][4], bf[4][2];
            #pragma unroll
            for (int mi = 0; mi < 4; mi++)
                ldsm4(af[mi][0], af[mi][1], af[mi][2], af[mi][3],
                      stg + aOff + mi * 16 * RSTR + kc * 2);
            ldsm4(bf[0][0], bf[0][1], bf[1][0], bf[1][1], stg + bOff + kc * 2);
            ldsm4(bf[2][0], bf[2][1], bf[3][0], bf[3][1], stg + bOff + 16 * RSTR + kc * 2);
            #pragma unroll
            for (int mi = 0; mi < 4; mi++)
                #pragma unroll
                for (int ni = 0; ni < 4; ni++)
                    mma_f16(acc[mi][ni], af[mi][0], af[mi][1], af[mi][2], af[mi][3],
                            bf[ni][0], bf[ni][1]);
        }
    }

    // ---- epilogue: bias, 16-way wu dot, hierarchical reduce, write d_stp ----
    #pragma unroll
    for (int ni = 0; ni < 4; ni++) {
        const float2 bb = *reinterpret_cast<const float2*>(&bm[nblk * 128 + wn * 32 + ni * 8 + tq * 2]);
        #pragma unroll
        for (int mi = 0; mi < 4; mi++) {
            acc[mi][ni][0] += bb.x; acc[mi][ni][1] += bb.y;
            acc[mi][ni][2] += bb.x; acc[mi][ni][3] += bb.y;
        }
    }

    __syncthreads();  // reuse stage region for st partials
    float* stS = reinterpret_cast<float*>(sm);   // [4 wn][128 rows][16 h]

    #pragma unroll
    for (int h = 0; h < 16; h++) {
        float2 wv[4];
        #pragma unroll
        for (int ni = 0; ni < 4; ni++)
            wv[ni] = *reinterpret_cast<const float2*>(&wuS[h * 256 + nblk * 128 + wn * 32 + ni * 8 + tq * 2]);
        #pragma unroll
        for (int mi = 0; mi < 4; mi++) {
            float p0 = 0.f, p1 = 0.f;
            #pragma unroll
            for (int ni = 0; ni < 4; ni++) {
                p0 += acc[mi][ni][0] * wv[ni].x + acc[mi][ni][1] * wv[ni].y;
                p1 += acc[mi][ni][2] * wv[ni].x + acc[mi][ni][3] * wv[ni].y;
            }
            p0 += __shfl_xor_sync(0xffffffffu, p0, 1);
            p0 += __shfl_xor_sync(0xffffffffu, p0, 2);
            p1 += __shfl_xor_sync(0xffffffffu, p1, 1);
            p1 += __shfl_xor_sync(0xffffffffu, p1, 2);
            if (tq == 0) {
                const int rl = wm * 64 + mi * 16 + g;
                stS[wn * 2048 + rl * 16 + h]       = p0;
                stS[wn * 2048 + (rl + 8) * 16 + h] = p1;
            }
        }
    }
    __syncthreads();
    {
        const int rowl = tid >> 1, hh = (tid & 1) * 8;
        float v[8];
        #pragma unroll
        for (int j = 0; j < 8; j++) {
            v[j] = stS[rowl * 16 + hh + j] + stS[2048 + rowl * 16 + hh + j]
                 + stS[4096 + rowl * 16 + hh + j] + stS[6144 + rowl * 16 + hh + j];
        }
        float* dst = &d_stp[nblk][(row0 + rowl) * 16 + hh];
        *reinterpret_cast<float4*>(dst)     = make_float4(v[0], v[1], v[2], v[3]);
        *reinterpret_cast<float4*>(dst + 4) = make_float4(v[4], v[5], v[6], v[7]);
    }
}

// ============================================================================
// Kernel 6: per-group softmax-weighted mean + tanh readout
// ============================================================================
__global__ void groups_kernel(float* __restrict__ out)
{
    __shared__ float sb[NPGC * 16];
    __shared__ float hv[8];
    const int g = blockIdx.x;
    const int tid = threadIdx.x;
    const float* __restrict__ b0 = &d_stp[0][g * (NPGC * 16)];
    const float* __restrict__ b1 = &d_stp[1][g * (NPGC * 16)];
    for (int i = tid; i < NPGC * 16; i += 256) sb[i] = b0[i] + b1[i];
    __syncthreads();

    const int h    = tid >> 5;
    const int lane = tid & 31;

    float mx = -1e30f;
    for (int r = lane; r < NPGC; r += 32) mx = fmaxf(mx, sb[r * 16 + h]);
    #pragma unroll
    for (int off = 16; off; off >>= 1) mx = fmaxf(mx, __shfl_xor_sync(0xffffffffu, mx, off));

    float num = 0.f, den = 0.f;
    for (int r = lane; r < NPGC; r += 32) {
        const float e = expf(sb[r * 16 + h] - mx);
        num = fmaf(e, sb[r * 16 + 8 + h], num);
        den += e;
    }
    #pragma unroll
    for (int off = 16; off; off >>= 1) {
        num += __shfl_xor_sync(0xffffffffu, num, off);
        den += __shfl_xor_sync(0xffffffffu, den, off);
    }
    if (lane == 0) hv[h] = num / den;
    __syncthreads();

    if (tid == 0) {
        float s = d_cconst[0];
        #pragma unroll
        for (int i = 0; i < 8; i++) s += hv[i];
        out[g] = tanhf(s);
    }
}

// ============================================================================
extern "C" void kernel_launch(void* const* d_in, const int* in_sizes, int n_in,
                              void* d_out, int out_size)
{
    const float* x0   = (const float*)d_in[0];
    const float* x1   = (const float*)d_in[1];
    const float* p0W  = (const float*)d_in[3];
    const float* p0b  = (const float*)d_in[4];
    const float* p0g  = (const float*)d_in[5];
    const float* p0be = (const float*)d_in[6];
    const float* p1W  = (const float*)d_in[7];
    const float* p1b  = (const float*)d_in[8];
    const float* p1g  = (const float*)d_in[9];
    const float* p1be = (const float*)d_in[10];
    const float* mW   = (const float*)d_in[11];
    const float* mb   = (const float*)d_in[12];
    const float* ipW  = (const float*)d_in[13];
    const float* ipb  = (const float*)d_in[14];
    const float* opW  = (const float*)d_in[15];
    const float* opb  = (const float*)d_in[16];
    const float* rW   = (const float*)d_in[17];
    const float* rb   = (const float*)d_in[18];
    float* out = (float*)d_out;

    cudaFuncSetAttribute(gemm1, cudaFuncAttributeMaxDynamicSharedMemorySize, SMEM1);
    cudaFuncSetAttribute(gemm2, cudaFuncAttributeMaxDynamicSharedMemorySize, SMEM2);

    prep_kernel<<<1, 256>>>(ipW, ipb, opW, opb, rW, rb);
    gemm1<<<dim3(MB, 2, 2), 256, SMEM1>>>(x0, x1, p0W, p0b, p1W, p1b);
    stats_partial<<<16, 256>>>();
    stats_final<<<2, 256>>>(p0g, p0be, p1g, p1be);
    gemm2<<<dim3(MB, 2), 256, SMEM2>>>(mW, mb);
    groups_kernel<<<NG, 256>>>(out);
}

// round 7
// speedup vs baseline: 4.0030x; 1.4398x over previous
#include <cuda_runtime.h>
#include <cuda_fp16.h>
#include <cstdint>
#include <math.h>

#define NROWS 204800
#define NG    2048
#define NPGC  100
#define MB    1600            // NROWS / 128

// ---- scratch (device globals; allocation forbidden) ----
__device__ __half d_Xh0[NROWS * 256];
__device__ __half d_Xh1[NROWS * 256];
__device__ __half d_Yh0[NROWS * 256];
__device__ __half d_Yh1[NROWS * 256];
__device__ __half d_Wh0[256 * 256];
__device__ __half d_Wh1[256 * 256];
__device__ __half d_Wmh[256 * 512];
__device__ float d_psum  [2 * MB * 256];
__device__ float d_psumsq[2 * MB * 256];
__device__ float d_psum2  [16 * 256];
__device__ float d_psumsq2[16 * 256];
__device__ float d_bnscale[512];
__device__ float d_bnshift[512];
__device__ __half d_bns_h[512];
__device__ __half d_bnh_h[512];
__device__ float d_wu[16 * 256];        // rows 0..7: ws_h ; rows 8..15: u_h
__device__ float d_cconst[1];
__device__ float d_stp[2][NROWS * 16];  // per-nblk partial [scores(8)|t(8)]

// ---- helpers ----
__device__ __forceinline__ unsigned hpack(float a, float b) {
    __half2 h = __floats2half2_rn(a, b);
    return *reinterpret_cast<unsigned*>(&h);
}
__device__ __forceinline__ void mma_f16(float c[4],
    unsigned a0, unsigned a1, unsigned a2, unsigned a3, unsigned b0, unsigned b1)
{
    asm volatile(
        "mma.sync.aligned.m16n8k16.row.col.f32.f16.f16.f32 "
        "{%0,%1,%2,%3},{%4,%5,%6,%7},{%8,%9},{%0,%1,%2,%3};"
        : "+f"(c[0]), "+f"(c[1]), "+f"(c[2]), "+f"(c[3])
        : "r"(a0), "r"(a1), "r"(a2), "r"(a3), "r"(b0), "r"(b1));
}
__device__ __forceinline__ void ldsm4(unsigned& r0, unsigned& r1, unsigned& r2, unsigned& r3,
                                      uint32_t addr)
{
    asm volatile("ldmatrix.sync.aligned.m8n8.x4.shared.b16 {%0,%1,%2,%3}, [%4];"
        : "=r"(r0), "=r"(r1), "=r"(r2), "=r"(r3) : "r"(addr));
}
__device__ __forceinline__ void cp16(uint32_t dst, const void* src) {
    asm volatile("cp.async.cg.shared.global [%0], [%1], 16;" :: "r"(dst), "l"(src) : "memory");
}
__device__ __forceinline__ void cp_commit() {
    asm volatile("cp.async.commit_group;" ::: "memory");
}
template<int N> __device__ __forceinline__ void cp_wait() {
    asm volatile("cp.async.wait_group %0;" :: "n"(N) : "memory");
}

// stage: A 128 rows x 128B (64 halfs) = 16 KB, B same; 32 KB per stage, 3 stages
constexpr int OPSTG   = 16384;
constexpr int STAGEB  = 32768;
constexpr int SMEM1   = 3 * STAGEB;            // 98304
constexpr int SMEM2   = 3 * STAGEB + 2048;     // + bns/bnh halves = 100352

// ============================================================================
// conversion kernels
// ============================================================================
__global__ void convert_x(const float* __restrict__ x0, const float* __restrict__ x1)
{
    const int total4 = NROWS * 64;   // float4 count per array
    for (int i = blockIdx.x * blockDim.x + threadIdx.x; i < 2 * total4;
         i += gridDim.x * blockDim.x) {
        const bool second = (i >= total4);
        const int k = second ? i - total4 : i;
        const float4 v = reinterpret_cast<const float4*>(second ? x1 : x0)[k];
        uint2 w;
        w.x = hpack(v.x, v.y);
        w.y = hpack(v.z, v.w);
        reinterpret_cast<uint2*>(second ? d_Xh1 : d_Xh0)[k] = w;
    }
}

__global__ void convert_w(const float* __restrict__ W0, const float* __restrict__ W1,
                          const float* __restrict__ Wm)
{
    int t = blockIdx.x * 256 + threadIdx.x;    // 0..65535
    const float* src; __half* dst; int k;
    if (t < 16384)      { src = W0; dst = d_Wh0; k = t; }
    else if (t < 32768) { src = W1; dst = d_Wh1; k = t - 16384; }
    else                { src = Wm; dst = d_Wmh; k = t - 32768; }
    const float4 v = reinterpret_cast<const float4*>(src)[k];
    uint2 w; w.x = hpack(v.x, v.y); w.y = hpack(v.z, v.w);
    reinterpret_cast<uint2*>(dst)[k] = w;
}

// ============================================================================
// Kernel 1: fold weights -> ws_h, u_h, cconst
// ============================================================================
__global__ void prep_kernel(const float* __restrict__ ipW, const float* __restrict__ ipb,
                            const float* __restrict__ opW, const float* __restrict__ opb,
                            const float* __restrict__ rW,  const float* __restrict__ rb)
{
    __shared__ float q[256];
    __shared__ float r2[256];
    __shared__ float red[256];
    const int tid = threadIdx.x;

    float s = 0.f;
    for (int k = 0; k < 256; k += 4) {
        float4 v = *reinterpret_cast<const float4*>(&ipW[tid * 256 + k]);
        s += v.x + v.y + v.z + v.w;
    }
    q[tid] = (s + ipb[tid]) * 0.17677669529663687f;

    float s2 = 0.f;
    for (int c = 0; c < 256; c++) s2 += rW[c] * opW[c * 256 + tid];
    r2[tid] = s2;
    __syncthreads();

    const int c = tid;
    for (int h = 0; h < 8; h++) {
        float a = 0.f, u = 0.f;
        #pragma unroll 8
        for (int d = 0; d < 32; d++) {
            a += q [h * 32 + d] * ipW[(256 + h * 32 + d) * 256 + c];
            u += r2[h * 32 + d] * ipW[(512 + h * 32 + d) * 256 + c];
        }
        d_wu[h * 256 + c]       = a;
        d_wu[(8 + h) * 256 + c] = u;
    }

    red[tid] = ipb[512 + tid] * r2[tid] + rW[tid] * opb[tid];
    __syncthreads();
    for (int off = 128; off; off >>= 1) {
        if (tid < off) red[tid] += red[tid + off];
        __syncthreads();
    }
    if (tid == 0) d_cconst[0] = red[0] + rb[0];
}

// ============================================================================
// Kernel 2: fp16 MMA GEMM Y = X @ W^T + b, cp.async 3-stage, BK=64
// grid (MB, 2 nblk, 2 mat), 256 threads
// ============================================================================
__global__ __launch_bounds__(256, 2)
void gemm1(const float* __restrict__ B0, const float* __restrict__ B1)
{
    extern __shared__ char sm[];
    const uint32_t sa = (uint32_t)__cvta_generic_to_shared(sm);

    const int mat  = blockIdx.z;
    const int nblk = blockIdx.y;
    const __half* __restrict__ Xh = mat ? d_Xh1 : d_Xh0;
    const __half* __restrict__ Wh = mat ? d_Wh1 : d_Wh0;
    const float*  __restrict__ bias = (mat ? B1 : B0) + nblk * 128;

    const int tid = threadIdx.x, lane = tid & 31, wid = tid >> 5;
    const int wm = wid >> 2, wn = wid & 3;
    const int g = lane >> 2, tq = lane & 3;
    const int row0 = blockIdx.x * 128;

    const __half* __restrict__ Arow0 = Xh + row0 * 256;
    const __half* __restrict__ Brow0 = Wh + nblk * 128 * 256;

    // per-lane ldmatrix constants
    const int xr   = (lane & 7) << 4;
    const int al16 = (lane >> 4) * 16;
    const int bl16 = ((lane >> 3) & 1) * 16;
    const uint32_t aRow = (uint32_t)((wm * 64 + (lane & 15)) * 128);
    const uint32_t bRow = (uint32_t)(OPSTG + (wn * 32 + (lane & 7) + ((lane >> 4) << 3)) * 128);

    // cp.async per-thread piece constants
    const int prow = tid >> 3;            // rows covered: tid..tid+... p = tid+256j -> row=(p>>3)
    const int pcb  = (tid & 7) * 16;      // byte col within row (same for all j since 256%8==0)
    const int pch  = (tid & 7) * 8;       // half col

    auto issue = [&](int s) {
        const uint32_t sb = sa + (s % 3) * STAGEB;
        const int kt = 64 * s;
        #pragma unroll
        for (int j = 0; j < 4; j++) {
            const int row = prow + 32 * j;
            const uint32_t d = sb + (uint32_t)(row * 128 + (pcb ^ ((row & 7) << 4)));
            cp16(d,         Arow0 + row * 256 + kt + pch);
            cp16(d + OPSTG, Brow0 + row * 256 + kt + pch);
        }
    };

    float acc[4][4][4];
    #pragma unroll
    for (int mi = 0; mi < 4; mi++)
        #pragma unroll
        for (int ni = 0; ni < 4; ni++)
            #pragma unroll
            for (int e = 0; e < 4; e++) acc[mi][ni][e] = 0.f;

    issue(0); cp_commit();
    issue(1); cp_commit();

    #pragma unroll 1
    for (int i = 0; i < 4; i++) {
        if (i < 3) cp_wait<1>(); else cp_wait<0>();
        __syncthreads();
        if (i + 2 < 4) { issue(i + 2); cp_commit(); }

        const uint32_t stg = sa + (i % 3) * STAGEB;
        #pragma unroll
        for (int kc2 = 0; kc2 < 128; kc2 += 32) {
            const int ac = (kc2 + al16) ^ xr;
            const int bc = (kc2 + bl16) ^ xr;
            unsigned af[4][4], bf[4][2];
            #pragma unroll
            for (int mi = 0; mi < 4; mi++)
                ldsm4(af[mi][0], af[mi][1], af[mi][2], af[mi][3],
                      stg + aRow + mi * 2048 + ac);
            ldsm4(bf[0][0], bf[0][1], bf[1][0], bf[1][1], stg + bRow + bc);
            ldsm4(bf[2][0], bf[2][1], bf[3][0], bf[3][1], stg + bRow + 2048 + bc);
            #pragma unroll
            for (int mi = 0; mi < 4; mi++)
                #pragma unroll
                for (int ni = 0; ni < 4; ni++)
                    mma_f16(acc[mi][ni], af[mi][0], af[mi][1], af[mi][2], af[mi][3],
                            bf[ni][0], bf[ni][1]);
        }
    }

    // ---- epilogue: bias, write Y (half), column stats ----
    float2 bb[4];
    #pragma unroll
    for (int ni = 0; ni < 4; ni++)
        bb[ni] = *reinterpret_cast<const float2*>(&bias[wn * 32 + ni * 8 + tq * 2]);
    #pragma unroll
    for (int mi = 0; mi < 4; mi++)
        #pragma unroll
        for (int ni = 0; ni < 4; ni++) {
            acc[mi][ni][0] += bb[ni].x; acc[mi][ni][1] += bb[ni].y;
            acc[mi][ni][2] += bb[ni].x; acc[mi][ni][3] += bb[ni].y;
        }

    __half* __restrict__ Y = mat ? d_Yh1 : d_Yh0;
    const int colbase = nblk * 128 + wn * 32;
    #pragma unroll
    for (int mi = 0; mi < 4; mi++) {
        const int R0 = row0 + wm * 64 + mi * 16 + g;
        #pragma unroll
        for (int ni = 0; ni < 4; ni++) {
            const int gc = colbase + ni * 8 + tq * 2;
            *reinterpret_cast<unsigned*>(&Y[R0 * 256 + gc])       = hpack(acc[mi][ni][0], acc[mi][ni][1]);
            *reinterpret_cast<unsigned*>(&Y[(R0 + 8) * 256 + gc]) = hpack(acc[mi][ni][2], acc[mi][ni][3]);
        }
    }

    __syncthreads();   // safe to reuse sm
    float* ssum = reinterpret_cast<float*>(sm);       // [2][128]
    float* ssq  = ssum + 256;
    #pragma unroll
    for (int ni = 0; ni < 4; ni++) {
        float s0 = 0.f, s1 = 0.f, q0 = 0.f, q1 = 0.f;
        #pragma unroll
        for (int mi = 0; mi < 4; mi++) {
            const float v0 = acc[mi][ni][0], v1 = acc[mi][ni][1];
            const float v2 = acc[mi][ni][2], v3 = acc[mi][ni][3];
            s0 += v0 + v2; s1 += v1 + v3;
            q0 += v0 * v0 + v2 * v2; q1 += v1 * v1 + v3 * v3;
        }
        #pragma unroll
        for (int off = 4; off < 32; off <<= 1) {
            s0 += __shfl_xor_sync(0xffffffffu, s0, off);
            s1 += __shfl_xor_sync(0xffffffffu, s1, off);
            q0 += __shfl_xor_sync(0xffffffffu, q0, off);
            q1 += __shfl_xor_sync(0xffffffffu, q1, off);
        }
        if (lane < 4) {
            const int lcol = wn * 32 + ni * 8 + tq * 2;
            ssum[wm * 128 + lcol] = s0;  ssum[wm * 128 + lcol + 1] = s1;
            ssq [wm * 128 + lcol] = q0;  ssq [wm * 128 + lcol + 1] = q1;
        }
    }
    __syncthreads();
    if (tid < 128) {
        const int gidx = (mat * MB + blockIdx.x) * 256 + nblk * 128 + tid;
        d_psum  [gidx] = ssum[tid] + ssum[128 + tid];
        d_psumsq[gidx] = ssq [tid] + ssq [128 + tid];
    }
}

// ============================================================================
// Kernels 3/4: deterministic stat reduction -> BN scale/shift
// ============================================================================
__global__ void stats_partial()
{
    const int mat = blockIdx.x >> 3;
    const int sl  = blockIdx.x & 7;
    const int col = threadIdx.x;
    float s = 0.f, q = 0.f;
    const int rb0 = sl * (MB / 8);
    for (int rbi = rb0; rbi < rb0 + (MB / 8); rbi++) {
        s += d_psum  [(mat * MB + rbi) * 256 + col];
        q += d_psumsq[(mat * MB + rbi) * 256 + col];
    }
    d_psum2  [blockIdx.x * 256 + col] = s;
    d_psumsq2[blockIdx.x * 256 + col] = q;
}

__global__ void stats_final(const float* __restrict__ g0, const float* __restrict__ be0,
                            const float* __restrict__ g1, const float* __restrict__ be1)
{
    const int mat = blockIdx.x;
    const int col = threadIdx.x;
    float s = 0.f, q = 0.f;
    #pragma unroll
    for (int sl = 0; sl < 8; sl++) {
        s += d_psum2  [(mat * 8 + sl) * 256 + col];
        q += d_psumsq2[(mat * 8 + sl) * 256 + col];
    }
    const float inv  = 1.0f / (float)NROWS;
    const float mean = s * inv;
    const float var  = fmaxf(q * inv - mean * mean, 0.f);
    const float* gg = mat ? g1 : g0;
    const float* bb = mat ? be1 : be0;
    const float sc = gg[col] * rsqrtf(var + 1e-5f);
    const float sh = bb[col] - mean * sc;
    d_bnscale[mat * 256 + col] = sc;
    d_bnshift[mat * 256 + col] = sh;
    d_bns_h[mat * 256 + col] = __float2half(sc);
    d_bnh_h[mat * 256 + col] = __float2half(sh);
}

// ============================================================================
// Kernel 5: fp16 MMA merge GEMM, cp.async 3-stage, BK=64, in-place BN+ReLU
// grid (MB, 2 nblk), 256 threads, K=512 (8 chunks)
// ============================================================================
__global__ __launch_bounds__(256, 2)
void gemm2(const float* __restrict__ bm)
{
    extern __shared__ char sm[];
    const uint32_t sa = (uint32_t)__cvta_generic_to_shared(sm);
    __half2* bns2 = reinterpret_cast<__half2*>(sm + 3 * STAGEB);        // 256 half2
    __half2* bnh2 = reinterpret_cast<__half2*>(sm + 3 * STAGEB + 1024); // 256 half2

    const int nblk = blockIdx.y;
    const int tid = threadIdx.x, lane = tid & 31, wid = tid >> 5;
    const int wm = wid >> 2, wn = wid & 3;
    const int g = lane >> 2, tq = lane & 3;
    const int row0 = blockIdx.x * 128;

    // extras load (visible after first pipeline sync)
    {
        const unsigned* s_src = reinterpret_cast<const unsigned*>(d_bns_h);
        const unsigned* h_src = reinterpret_cast<const unsigned*>(d_bnh_h);
        if (tid < 256) {
            reinterpret_cast<unsigned*>(bns2)[tid] = s_src[tid];
            reinterpret_cast<unsigned*>(bnh2)[tid] = h_src[tid];
        }
    }

    const __half* __restrict__ Brow0 = d_Wmh + nblk * 128 * 512;

    const int xr   = (lane & 7) << 4;
    const int al16 = (lane >> 4) * 16;
    const int bl16 = ((lane >> 3) & 1) * 16;
    const uint32_t aRow = (uint32_t)((wm * 64 + (lane & 15)) * 128);
    const uint32_t bRow = (uint32_t)(OPSTG + (wn * 32 + (lane & 7) + ((lane >> 4) << 3)) * 128);

    const int prow = tid >> 3;
    const int pcb  = (tid & 7) * 16;
    const int pch  = (tid & 7) * 8;

    auto issue = [&](int s) {
        const uint32_t sb = sa + (s % 3) * STAGEB;
        const int kt = 64 * s;
        const __half* __restrict__ Ys = (kt < 256) ? d_Yh0 : d_Yh1;
        const int ko = kt & 255;
        #pragma unroll
        for (int j = 0; j < 4; j++) {
            const int row = prow + 32 * j;
            const uint32_t d = sb + (uint32_t)(row * 128 + (pcb ^ ((row & 7) << 4)));
            cp16(d,         Ys + (row0 + row) * 256 + ko + pch);
            cp16(d + OPSTG, Brow0 + row * 512 + kt + pch);
        }
    };

    float acc[4][4][4];
    #pragma unroll
    for (int mi = 0; mi < 4; mi++)
        #pragma unroll
        for (int ni = 0; ni < 4; ni++)
            #pragma unroll
            for (int e = 0; e < 4; e++) acc[mi][ni][e] = 0.f;

    issue(0); cp_commit();
    issue(1); cp_commit();

    const __half2 z2 = __float2half2_rn(0.f);

    #pragma unroll 1
    for (int i = 0; i < 8; i++) {
        if (i < 7) cp_wait<1>(); else cp_wait<0>();
        __syncthreads();
        if (i + 2 < 8) { issue(i + 2); cp_commit(); }

        // in-place BN + ReLU on the A stage (half2 arithmetic)
        char* stgc = sm + (i % 3) * STAGEB;
        const int kt = 64 * i;
        #pragma unroll
        for (int j = 0; j < 4; j++) {
            const int row = prow + 32 * j;
            __half2* ap = reinterpret_cast<__half2*>(stgc + row * 128 + (pcb ^ ((row & 7) << 4)));
            const int si = (kt + pch) >> 1;     // half2 index, multiple of 4
            const __half2 s0 = bns2[si], s1 = bns2[si + 1], s2 = bns2[si + 2], s3 = bns2[si + 3];
            const __half2 h0 = bnh2[si], h1 = bnh2[si + 1], h2 = bnh2[si + 2], h3 = bnh2[si + 3];
            __half2 v0 = ap[0], v1 = ap[1], v2 = ap[2], v3 = ap[3];
            v0 = __hmax2(__hfma2(v0, s0, h0), z2);
            v1 = __hmax2(__hfma2(v1, s1, h1), z2);
            v2 = __hmax2(__hfma2(v2, s2, h2), z2);
            v3 = __hmax2(__hfma2(v3, s3, h3), z2);
            ap[0] = v0; ap[1] = v1; ap[2] = v2; ap[3] = v3;
        }
        __syncthreads();

        const uint32_t stg = sa + (i % 3) * STAGEB;
        #pragma unroll
        for (int kc2 = 0; kc2 < 128; kc2 += 32) {
            const int ac = (kc2 + al16) ^ xr;
            const int bc = (kc2 + bl16) ^ xr;
            unsigned af[4][4], bf[4][2];
            #pragma unroll
            for (int mi = 0; mi < 4; mi++)
                ldsm4(af[mi][0], af[mi][1], af[mi][2], af[mi][3],
                      stg + aRow + mi * 2048 + ac);
            ldsm4(bf[0][0], bf[0][1], bf[1][0], bf[1][1], stg + bRow + bc);
            ldsm4(bf[2][0], bf[2][1], bf[3][0], bf[3][1], stg + bRow + 2048 + bc);
            #pragma unroll
            for (int mi = 0; mi < 4; mi++)
                #pragma unroll
                for (int ni = 0; ni < 4; ni++)
                    mma_f16(acc[mi][ni], af[mi][0], af[mi][1], af[mi][2], af[mi][3],
                            bf[ni][0], bf[ni][1]);
        }
    }

    // ---- epilogue: bias, 16-way wu dot, hierarchical reduce, write d_stp ----
    #pragma unroll
    for (int ni = 0; ni < 4; ni++) {
        const float2 bb = *reinterpret_cast<const float2*>(&bm[nblk * 128 + wn * 32 + ni * 8 + tq * 2]);
        #pragma unroll
        for (int mi = 0; mi < 4; mi++) {
            acc[mi][ni][0] += bb.x; acc[mi][ni][1] += bb.y;
            acc[mi][ni][2] += bb.x; acc[mi][ni][3] += bb.y;
        }
    }

    __syncthreads();  // reuse stage region
    float* wuS = reinterpret_cast<float*>(sm);          // [16][128] this nblk half
    float* stS = reinterpret_cast<float*>(sm) + 2048;   // [4 wn][128 rows][16 h]
    #pragma unroll
    for (int j = 0; j < 8; j++) {
        const int i2 = tid + 256 * j;
        const int h = i2 >> 7, c = i2 & 127;
        wuS[i2] = d_wu[h * 256 + nblk * 128 + c];
    }
    __syncthreads();

    #pragma unroll
    for (int h = 0; h < 16; h++) {
        float2 wv[4];
        #pragma unroll
        for (int ni = 0; ni < 4; ni++)
            wv[ni] = *reinterpret_cast<const float2*>(&wuS[h * 128 + wn * 32 + ni * 8 + tq * 2]);
        #pragma unroll
        for (int mi = 0; mi < 4; mi++) {
            float p0 = 0.f, p1 = 0.f;
            #pragma unroll
            for (int ni = 0; ni < 4; ni++) {
                p0 += acc[mi][ni][0] * wv[ni].x + acc[mi][ni][1] * wv[ni].y;
                p1 += acc[mi][ni][2] * wv[ni].x + acc[mi][ni][3] * wv[ni].y;
            }
            p0 += __shfl_xor_sync(0xffffffffu, p0, 1);
            p0 += __shfl_xor_sync(0xffffffffu, p0, 2);
            p1 += __shfl_xor_sync(0xffffffffu, p1, 1);
            p1 += __shfl_xor_sync(0xffffffffu, p1, 2);
            if (tq == 0) {
                const int rl = wm * 64 + mi * 16 + g;
                stS[wn * 2048 + rl * 16 + h]       = p0;
                stS[wn * 2048 + (rl + 8) * 16 + h] = p1;
            }
        }
    }
    __syncthreads();
    {
        const int rowl = tid >> 1, hh = (tid & 1) * 8;
        float v[8];
        #pragma unroll
        for (int j = 0; j < 8; j++) {
            v[j] = stS[rowl * 16 + hh + j] + stS[2048 + rowl * 16 + hh + j]
                 + stS[4096 + rowl * 16 + hh + j] + stS[6144 + rowl * 16 + hh + j];
        }
        float* dst = &d_stp[nblk][(row0 + rowl) * 16 + hh];
        *reinterpret_cast<float4*>(dst)     = make_float4(v[0], v[1], v[2], v[3]);
        *reinterpret_cast<float4*>(dst + 4) = make_float4(v[4], v[5], v[6], v[7]);
    }
}

// ============================================================================
// Kernel 6: per-group softmax-weighted mean + tanh readout
// ============================================================================
__global__ void groups_kernel(float* __restrict__ out)
{
    __shared__ float sb[NPGC * 16];
    __shared__ float hv[8];
    const int g = blockIdx.x;
    const int tid = threadIdx.x;
    const float* __restrict__ b0 = &d_stp[0][g * (NPGC * 16)];
    const float* __restrict__ b1 = &d_stp[1][g * (NPGC * 16)];
    for (int i = tid; i < NPGC * 16; i += 256) sb[i] = b0[i] + b1[i];
    __syncthreads();

    const int h    = tid >> 5;
    const int lane = tid & 31;

    float mx = -1e30f;
    for (int r = lane; r < NPGC; r += 32) mx = fmaxf(mx, sb[r * 16 + h]);
    #pragma unroll
    for (int off = 16; off; off >>= 1) mx = fmaxf(mx, __shfl_xor_sync(0xffffffffu, mx, off));

    float num = 0.f, den = 0.f;
    for (int r = lane; r < NPGC; r += 32) {
        const float e = expf(sb[r * 16 + h] - mx);
        num = fmaf(e, sb[r * 16 + 8 + h], num);
        den += e;
    }
    #pragma unroll
    for (int off = 16; off; off >>= 1) {
        num += __shfl_xor_sync(0xffffffffu, num, off);
        den += __shfl_xor_sync(0xffffffffu, den, off);
    }
    if (lane == 0) hv[h] = num / den;
    __syncthreads();

    if (tid == 0) {
        float s = d_cconst[0];
        #pragma unroll
        for (int i = 0; i < 8; i++) s += hv[i];
        out[g] = tanhf(s);
    }
}

// ============================================================================
extern "C" void kernel_launch(void* const* d_in, const int* in_sizes, int n_in,
                              void* d_out, int out_size)
{
    const float* x0   = (const float*)d_in[0];
    const float* x1   = (const float*)d_in[1];
    const float* p0W  = (const float*)d_in[3];
    const float* p0b  = (const float*)d_in[4];
    const float* p0g  = (const float*)d_in[5];
    const float* p0be = (const float*)d_in[6];
    const float* p1W  = (const float*)d_in[7];
    const float* p1b  = (const float*)d_in[8];
    const float* p1g  = (const float*)d_in[9];
    const float* p1be = (const float*)d_in[10];
    const float* mW   = (const float*)d_in[11];
    const float* mb   = (const float*)d_in[12];
    const float* ipW  = (const float*)d_in[13];
    const float* ipb  = (const float*)d_in[14];
    const float* opW  = (const float*)d_in[15];
    const float* opb  = (const float*)d_in[16];
    const float* rW   = (const float*)d_in[17];
    const float* rb   = (const float*)d_in[18];
    float* out = (float*)d_out;

    cudaFuncSetAttribute(gemm1, cudaFuncAttributeMaxDynamicSharedMemorySize, SMEM1);
    cudaFuncSetAttribute(gemm2, cudaFuncAttributeMaxDynamicSharedMemorySize, SMEM2);

    prep_kernel<<<1, 256>>>(ipW, ipb, opW, opb, rW, rb);
    convert_w<<<256, 256>>>(p0W, p1W, mW);
    convert_x<<<2048, 256>>>(x0, x1);
    gemm1<<<dim3(MB, 2, 2), 256, SMEM1>>>(p0b, p1b);
    stats_partial<<<16, 256>>>();
    stats_final<<<2, 256>>>(p0g, p0be, p1g, p1be);
    gemm2<<<dim3(MB, 2), 256, SMEM2>>>(mb);
    groups_kernel<<<NG, 256>>>(out);
}